// round 2
// baseline (speedup 1.0000x reference)
#include <cuda_runtime.h>
#include <math.h>

#define PTS   4096      // B*N = 8*512
#define DM    256

// ---------------- scratch (device globals; no allocations allowed) ----------
__device__ float g_pe[PTS * 256];
__device__ float g_spatial[PTS * 256];
__device__ float g_feat[PTS * 16];
__device__ float g_fe1[PTS * 128];
__device__ float g_h1[PTS * 128];
__device__ float g_fe2[PTS * 256];
__device__ float g_freq[PTS * 256];
__device__ float g_q[PTS * 256];
__device__ float g_k[PTS * 256];
__device__ float g_v[PTS * 256];
__device__ float g_o[PTS * 256];
__device__ float g_ao[PTS * 256];
__device__ float g_x[PTS * 256];
__device__ float g_ffh[PTS * 512];
__device__ float g_ff2[PTS * 256];
__device__ float g_x2[PTS * 256];

__device__ __forceinline__ float gelu_f(float x) {
    return 0.5f * x * (1.0f + erff(x * 0.7071067811865475f));
}

// ---------------- block reduce ----------------------------------------------
__device__ __forceinline__ float blockReduceSum(float v, float* sh) {
    int lane = threadIdx.x & 31, wid = threadIdx.x >> 5, nw = blockDim.x >> 5;
#pragma unroll
    for (int o = 16; o; o >>= 1) v += __shfl_xor_sync(0xffffffffu, v, o);
    __syncthreads();               // protect sh reuse across calls
    if (lane == 0) sh[wid] = v;
    __syncthreads();
    float r = 0.0f;
    if (wid == 0) {
        r = (lane < nw) ? sh[lane] : 0.0f;
#pragma unroll
        for (int o = 16; o; o >>= 1) r += __shfl_xor_sync(0xffffffffu, r, o);
        if (lane == 0) sh[0] = r;
    }
    __syncthreads();
    return sh[0];
}

// ---------------- PE kernel: one block per point, tid = channel -------------
__global__ void __launch_bounds__(256) pe_kernel(const float* __restrict__ coords,
                                                 float* __restrict__ pe) {
    int pt = blockIdx.x;
    int t = threadIdx.x;
    float cx = coords[pt * 2] * (1.0f / 1024.0f);
    float cy = coords[pt * 2 + 1] * (1.0f / 1024.0f);
    int comp = t >> 6;            // 0: sin ax, 1: cos ax, 2: sin ay, 3: cos ay
    int i = t & 63;
    float dimt = powf(10000.0f, (float)(2 * i) / 64.0f);
    float coord = (comp < 2) ? cx : cy;
    float arg = coord * 6.283185307179586f / dimt;
    float val = (comp & 1) ? cosf(arg) : sinf(arg);
    pe[(size_t)pt * 256 + t] = val;
}

// ---------------- patch gather + 2D DFT + radial binning --------------------
__global__ void __launch_bounds__(256) fft_feat_kernel(const float* __restrict__ image,
                                                       const float* __restrict__ coords,
                                                       const float* __restrict__ fbi,
                                                       float* __restrict__ feat) {
    int pt = blockIdx.x;
    int b = pt >> 9;              // N = 512
    int tid = threadIdx.x;

    __shared__ float patch[16][16];
    __shared__ float Rre[16][9], Rim[16][9];
    __shared__ float twc[16], tws[16];
    __shared__ float bmag[8], bang[8];
    __shared__ int bcnt[8];
    __shared__ float smf[8];
    __shared__ int spx, spy;

    if (tid == 0) {
        float cx = coords[pt * 2];
        float cy = coords[pt * 2 + 1];
        int px = (int)cx; px = min(max(px, 8), 1015);
        int py = (int)cy; py = min(max(py, 8), 1015);
        spx = px; spy = py;
        // softmax over fbi (8 values)
        float mx = -1e30f;
        for (int i = 0; i < 8; i++) mx = fmaxf(mx, fbi[i]);
        float s = 0.0f;
        for (int i = 0; i < 8; i++) { float e = expf(fbi[i] - mx); smf[i] = e; s += e; }
        float inv = 1.0f / s;
        for (int i = 0; i < 8; i++) smf[i] *= inv;
    }
    if (tid < 16) {
        // exact zeros at multiples of pi (match FFT's structurally-zero imag parts)
        twc[tid] = cospif((float)tid / 8.0f);
        tws[tid] = sinpif(-(float)tid / 8.0f);
    }
    if (tid < 8) { bmag[tid] = 0.0f; bang[tid] = 0.0f; bcnt[tid] = 0; }
    __syncthreads();

    int y = tid >> 4, x = tid & 15;
    int yy = spy - 8 + y, xx = spx - 8 + x;
    const float* imb = image + (size_t)b * 3u * 1024u * 1024u;
    size_t off = (size_t)yy * 1024 + xx;
    float gsum = imb[off] + imb[1048576u + off] + imb[2097152u + off];
    patch[y][x] = gsum * (1.0f / 3.0f);
    __syncthreads();

    if (tid < 144) {          // row DFT: (y, kx)
        int ry = tid / 9, kx = tid % 9;
        float re = 0.0f, im = 0.0f;
#pragma unroll
        for (int j = 0; j < 16; j++) {
            float pv = patch[ry][j];
            int t = (kx * j) & 15;
            re += pv * twc[t];
            im += pv * tws[t];
        }
        Rre[ry][kx] = re;
        Rim[ry][kx] = im;
    }
    __syncthreads();

    if (tid < 144) {          // col DFT: (ky, kx)
        int ky = tid / 9, kx = tid % 9;
        float re = 0.0f, im = 0.0f;
#pragma unroll
        for (int j = 0; j < 16; j++) {
            int t = (ky * j) & 15;
            float c = twc[t], s = tws[t];
            float ar = Rre[j][kx], ai = Rim[j][kx];
            re += ar * c - ai * s;
            im += ar * s + ai * c;
        }
        re *= 0.0625f;        // ortho norm 1/sqrt(256)
        im *= 0.0625f;
        float mag = sqrtf(re * re + im * im);
        float ang = atan2f(im, re);

        // radial bin, replicating numpy double-precision linspace/searchsorted
        double fy = (ky < 8) ? (double)ky / 16.0 : ((double)ky - 16.0) / 16.0;
        double fx = (double)kx / 16.0;
        double r = sqrt(fx * fx + fy * fy);
        double maxr = 0.7071067811865476 + 1e-6;
        double step = maxr / 8.0;
        int bi = 0;
#pragma unroll
        for (int k = 1; k < 9; k++) if (r >= (double)k * step) bi = k;
        if (bi > 7) bi = 7;
        atomicAdd(&bmag[bi], mag);
        atomicAdd(&bang[bi], ang);
        atomicAdd(&bcnt[bi], 1);
    }
    __syncthreads();

    if (tid < 8) {
        float c = (float)max(bcnt[tid], 1);
        feat[(size_t)pt * 16 + tid]     = bmag[tid] / c * smf[tid];
        feat[(size_t)pt * 16 + 8 + tid] = bang[tid] / c;
    }
}

// ---------------- tiled SGEMM: C[M,N] = A[M,K] @ W[N,K]^T + bias -----------
// EP: 0 = bias only, 1 = bias + gelu, 2 = bias + type_emb[label[row]]
template <int EP>
__global__ void __launch_bounds__(256) gemm_k(const float* __restrict__ A,
                                              const float* __restrict__ W,
                                              const float* __restrict__ bias,
                                              float* __restrict__ C,
                                              int M, int N, int K,
                                              const int* __restrict__ labels,
                                              const float* __restrict__ temb) {
    __shared__ __align__(16) float As[16][68];
    __shared__ __align__(16) float Ws[16][68];
    const int tx = threadIdx.x & 15, ty = threadIdx.x >> 4;
    const int m0 = blockIdx.y << 6, n0 = blockIdx.x << 6;
    const int lrow = threadIdx.x >> 2;
    const int lk4 = (threadIdx.x & 3) << 2;
    float acc[4][4] = {};

    for (int k0 = 0; k0 < K; k0 += 16) {
        float4 av = *(const float4*)(A + (size_t)(m0 + lrow) * K + k0 + lk4);
        float4 wv = *(const float4*)(W + (size_t)(n0 + lrow) * K + k0 + lk4);
        As[lk4 + 0][lrow] = av.x; As[lk4 + 1][lrow] = av.y;
        As[lk4 + 2][lrow] = av.z; As[lk4 + 3][lrow] = av.w;
        Ws[lk4 + 0][lrow] = wv.x; Ws[lk4 + 1][lrow] = wv.y;
        Ws[lk4 + 2][lrow] = wv.z; Ws[lk4 + 3][lrow] = wv.w;
        __syncthreads();
#pragma unroll
        for (int kk = 0; kk < 16; kk++) {
            float4 a4 = *(const float4*)&As[kk][ty << 2];
            float4 b4 = *(const float4*)&Ws[kk][tx << 2];
            float ar[4] = {a4.x, a4.y, a4.z, a4.w};
            float br[4] = {b4.x, b4.y, b4.z, b4.w};
#pragma unroll
            for (int i = 0; i < 4; i++)
#pragma unroll
                for (int j = 0; j < 4; j++)
                    acc[i][j] += ar[i] * br[j];
        }
        __syncthreads();
    }

#pragma unroll
    for (int i = 0; i < 4; i++) {
        int row = m0 + (ty << 2) + i;
        const float* trow = nullptr;
        if (EP == 2) trow = temb + (size_t)labels[row] * 256;
#pragma unroll
        for (int j = 0; j < 4; j++) {
            int col = n0 + (tx << 2) + j;
            float v = acc[i][j] + bias[col];
            if (EP == 1) v = gelu_f(v);
            if (EP == 2) v += trow[col];
            C[(size_t)row * N + col] = v;
        }
    }
}

// ---------------- layer norm (optionally gelu / residual) -------------------
template <int WIDTH, bool GELU, bool RES>
__global__ void __launch_bounds__(WIDTH) ln_kernel(const float* __restrict__ in,
                                                   const float* __restrict__ res,
                                                   const float* __restrict__ g,
                                                   const float* __restrict__ bv,
                                                   float* __restrict__ out) {
    __shared__ float sh[32];
    int row = blockIdx.x, t = threadIdx.x;
    float v = in[(size_t)row * WIDTH + t];
    if (RES) v += res[(size_t)row * WIDTH + t];
    float s = blockReduceSum(v, sh);
    float mean = s * (1.0f / WIDTH);
    float d = v - mean;
    float s2 = blockReduceSum(d * d, sh);
    float var = s2 * (1.0f / WIDTH);
    float o = g[t] * d * rsqrtf(var + 1e-5f) + bv[t];
    if (GELU) o = gelu_f(o);
    out[(size_t)row * WIDTH + t] = o;
}

// ---------------- attention: block per (b, h, 16-q tile) --------------------
__global__ void __launch_bounds__(256) attn_kernel(const float* __restrict__ Q,
                                                   const float* __restrict__ Kt,
                                                   const float* __restrict__ V,
                                                   float* __restrict__ O) {
    __shared__ __align__(16) float Qs[16][64];
    __shared__ __align__(16) float Ks[32][64];
    __shared__ float S[16][512];
    __shared__ float rs[16];
    int b = blockIdx.z, h = blockIdx.y, q0 = blockIdx.x << 4;
    int tid = threadIdx.x;
    size_t baseQ = ((size_t)(b * 512 + q0)) * 256 + h * 64;

    {
        int qi = tid >> 4, dg = (tid & 15) << 2;
        *(float4*)&Qs[qi][dg] = *(const float4*)(Q + baseQ + (size_t)qi * 256 + dg);
    }

    for (int kc = 0; kc < 512; kc += 32) {
        __syncthreads();
#pragma unroll
        for (int r = 0; r < 2; r++) {
            int idx = tid + (r << 8);
            int ki = idx >> 4, dg = (idx & 15) << 2;
            *(float4*)&Ks[ki][dg] =
                *(const float4*)(Kt + ((size_t)(b * 512 + kc + ki)) * 256 + h * 64 + dg);
        }
        __syncthreads();
#pragma unroll
        for (int r = 0; r < 2; r++) {
            int idx = tid + (r << 8);
            int qi = idx >> 5, ki = idx & 31;
            float s = 0.0f;
#pragma unroll
            for (int d = 0; d < 64; d += 4) {
                float4 qa = *(const float4*)&Qs[qi][d];
                float4 kb = *(const float4*)&Ks[ki][d];
                s += qa.x * kb.x + qa.y * kb.y + qa.z * kb.z + qa.w * kb.w;
            }
            S[qi][kc + ki] = s * 0.125f;
        }
    }
    __syncthreads();

    {   // softmax (unnormalized exp; keep row sums)
        int w = tid >> 5, lane = tid & 31;
        for (int r = w * 2; r < w * 2 + 2; r++) {
            float m = -1e30f;
            for (int j = lane; j < 512; j += 32) m = fmaxf(m, S[r][j]);
#pragma unroll
            for (int o = 16; o; o >>= 1) m = fmaxf(m, __shfl_xor_sync(0xffffffffu, m, o));
            float sum = 0.0f;
            for (int j = lane; j < 512; j += 32) {
                float e = expf(S[r][j] - m);
                S[r][j] = e;
                sum += e;
            }
#pragma unroll
            for (int o = 16; o; o >>= 1) sum += __shfl_xor_sync(0xffffffffu, sum, o);
            if (lane == 0) rs[r] = sum;
        }
    }
    __syncthreads();

    int qi = tid >> 4, d0 = (tid & 15) << 2;
    float acc0 = 0, acc1 = 0, acc2 = 0, acc3 = 0;
    for (int kc = 0; kc < 512; kc += 32) {
        __syncthreads();
#pragma unroll
        for (int r = 0; r < 2; r++) {
            int idx = tid + (r << 8);
            int ki = idx >> 4, dg = (idx & 15) << 2;
            *(float4*)&Ks[ki][dg] =
                *(const float4*)(V + ((size_t)(b * 512 + kc + ki)) * 256 + h * 64 + dg);
        }
        __syncthreads();
#pragma unroll
        for (int ki = 0; ki < 32; ki++) {
            float p = S[qi][kc + ki];
            float4 vv = *(const float4*)&Ks[ki][d0];
            acc0 += p * vv.x; acc1 += p * vv.y; acc2 += p * vv.z; acc3 += p * vv.w;
        }
    }
    float inv = 1.0f / rs[qi];
    float4 o4;
    o4.x = acc0 * inv; o4.y = acc1 * inv; o4.z = acc2 * inv; o4.w = acc3 * inv;
    *(float4*)(O + baseQ + (size_t)qi * 256 + d0) = o4;
}

// ---------------- launch ----------------------------------------------------
extern "C" void kernel_launch(void* const* d_in, const int* in_sizes, int n_in,
                              void* d_out, int out_size) {
    (void)in_sizes; (void)n_in; (void)out_size;
    const float* image  = (const float*)d_in[0];
    const float* coords = (const float*)d_in[1];
    const int*   labels = (const int*)d_in[2];
    const float* pe_w   = (const float*)d_in[3];
    const float* pe_b   = (const float*)d_in[4];
    const float* temb   = (const float*)d_in[5];
    const float* fbi    = (const float*)d_in[6];
    const float* fe1_w  = (const float*)d_in[7];
    const float* fe1_b  = (const float*)d_in[8];
    const float* feln1g = (const float*)d_in[9];
    const float* feln1b = (const float*)d_in[10];
    const float* fe2_w  = (const float*)d_in[11];
    const float* fe2_b  = (const float*)d_in[12];
    const float* feln2g = (const float*)d_in[13];
    const float* feln2b = (const float*)d_in[14];
    const float* in_w   = (const float*)d_in[15];
    const float* in_b   = (const float*)d_in[16];
    const float* ao_w   = (const float*)d_in[17];
    const float* ao_b   = (const float*)d_in[18];
    const float* n1_g   = (const float*)d_in[19];
    const float* n1_b   = (const float*)d_in[20];
    const float* f1_w   = (const float*)d_in[21];
    const float* f1_b   = (const float*)d_in[22];
    const float* f2_w   = (const float*)d_in[23];
    const float* f2_b   = (const float*)d_in[24];
    const float* n2_g   = (const float*)d_in[25];
    const float* n2_b   = (const float*)d_in[26];
    const float* op_w   = (const float*)d_in[27];
    const float* op_b   = (const float*)d_in[28];
    float* out = (float*)d_out;

    float *p_pe, *p_spatial, *p_feat, *p_fe1, *p_h1, *p_fe2, *p_freq;
    float *p_q, *p_k, *p_v, *p_o, *p_ao, *p_x, *p_ffh, *p_ff2, *p_x2;
    cudaGetSymbolAddress((void**)&p_pe, g_pe);
    cudaGetSymbolAddress((void**)&p_spatial, g_spatial);
    cudaGetSymbolAddress((void**)&p_feat, g_feat);
    cudaGetSymbolAddress((void**)&p_fe1, g_fe1);
    cudaGetSymbolAddress((void**)&p_h1, g_h1);
    cudaGetSymbolAddress((void**)&p_fe2, g_fe2);
    cudaGetSymbolAddress((void**)&p_freq, g_freq);
    cudaGetSymbolAddress((void**)&p_q, g_q);
    cudaGetSymbolAddress((void**)&p_k, g_k);
    cudaGetSymbolAddress((void**)&p_v, g_v);
    cudaGetSymbolAddress((void**)&p_o, g_o);
    cudaGetSymbolAddress((void**)&p_ao, g_ao);
    cudaGetSymbolAddress((void**)&p_x, g_x);
    cudaGetSymbolAddress((void**)&p_ffh, g_ffh);
    cudaGetSymbolAddress((void**)&p_ff2, g_ff2);
    cudaGetSymbolAddress((void**)&p_x2, g_x2);

    // 1) sinusoidal PE
    pe_kernel<<<PTS, 256>>>(coords, p_pe);
    // 2) spatial = PE @ pe_w^T + pe_b + type_emb[label]
    gemm_k<2><<<dim3(4, 64), 256>>>(p_pe, pe_w, pe_b, p_spatial, PTS, 256, 256, labels, temb);
    // 3) patch FFT features (16 per point)
    fft_feat_kernel<<<PTS, 256>>>(image, coords, fbi, p_feat);
    // 4) freq MLP
    gemm_k<0><<<dim3(2, 64), 256>>>(p_feat, fe1_w, fe1_b, p_fe1, PTS, 128, 16, nullptr, nullptr);
    ln_kernel<128, true, false><<<PTS, 128>>>(p_fe1, nullptr, feln1g, feln1b, p_h1);
    gemm_k<0><<<dim3(4, 64), 256>>>(p_h1, fe2_w, fe2_b, p_fe2, PTS, 256, 128, nullptr, nullptr);
    ln_kernel<256, false, false><<<PTS, 256>>>(p_fe2, nullptr, feln2g, feln2b, p_freq);
    // 5) QKV projections
    gemm_k<0><<<dim3(4, 64), 256>>>(p_spatial, in_w,             in_b,       p_q, PTS, 256, 256, nullptr, nullptr);
    gemm_k<0><<<dim3(4, 64), 256>>>(p_freq,    in_w + 256 * 256, in_b + 256, p_k, PTS, 256, 256, nullptr, nullptr);
    gemm_k<0><<<dim3(4, 64), 256>>>(p_freq,    in_w + 512 * 256, in_b + 512, p_v, PTS, 256, 256, nullptr, nullptr);
    // 6) attention
    attn_kernel<<<dim3(32, 4, 8), 256>>>(p_q, p_k, p_v, p_o);
    // 7) attn out proj + residual LN
    gemm_k<0><<<dim3(4, 64), 256>>>(p_o, ao_w, ao_b, p_ao, PTS, 256, 256, nullptr, nullptr);
    ln_kernel<256, false, true><<<PTS, 256>>>(p_ao, p_spatial, n1_g, n1_b, p_x);
    // 8) FFN
    gemm_k<1><<<dim3(8, 64), 256>>>(p_x, f1_w, f1_b, p_ffh, PTS, 512, 256, nullptr, nullptr);
    gemm_k<0><<<dim3(4, 64), 256>>>(p_ffh, f2_w, f2_b, p_ff2, PTS, 256, 512, nullptr, nullptr);
    ln_kernel<256, false, true><<<PTS, 256>>>(p_ff2, p_x, n2_g, n2_b, p_x2);
    // 9) output projection
    gemm_k<0><<<dim3(4, 64), 256>>>(p_x2, op_w, op_b, out, PTS, 256, 256, nullptr, nullptr);
}

// round 3
// speedup vs baseline: 1.0643x; 1.0643x over previous
#include <cuda_runtime.h>
#include <math.h>

#define PTS   4096      // B*N = 8*512

// ---------------- scratch (device globals; no allocations allowed) ----------
__device__ float g_pe[PTS * 256];
__device__ float g_spatial[PTS * 256];
__device__ float g_feat[PTS * 16];
__device__ float g_fe1[PTS * 128];
__device__ float g_h1[PTS * 128];
__device__ float g_fe2[PTS * 256];
__device__ float g_freq[PTS * 256];
__device__ float g_q[PTS * 256];
__device__ float g_kv[PTS * 512];
__device__ float g_o[PTS * 256];
__device__ float g_ao[PTS * 256];
__device__ float g_x[PTS * 256];
__device__ float g_ffh[PTS * 512];
__device__ float g_ff2[PTS * 256];
__device__ float g_x2[PTS * 256];

__device__ __forceinline__ float gelu_f(float x) {
    return 0.5f * x * (1.0f + erff(x * 0.7071067811865475f));
}

// ---------------- block reduce ----------------------------------------------
__device__ __forceinline__ float blockReduceSum(float v, float* sh) {
    int lane = threadIdx.x & 31, wid = threadIdx.x >> 5, nw = blockDim.x >> 5;
#pragma unroll
    for (int o = 16; o; o >>= 1) v += __shfl_xor_sync(0xffffffffu, v, o);
    __syncthreads();
    if (lane == 0) sh[wid] = v;
    __syncthreads();
    float r = 0.0f;
    if (wid == 0) {
        r = (lane < nw) ? sh[lane] : 0.0f;
#pragma unroll
        for (int o = 16; o; o >>= 1) r += __shfl_xor_sync(0xffffffffu, r, o);
        if (lane == 0) sh[0] = r;
    }
    __syncthreads();
    return sh[0];
}

// ---------------- PE kernel -------------------------------------------------
__global__ void __launch_bounds__(256) pe_kernel(const float* __restrict__ coords,
                                                 float* __restrict__ pe) {
    int pt = blockIdx.x;
    int t = threadIdx.x;
    float cx = coords[pt * 2] * (1.0f / 1024.0f);
    float cy = coords[pt * 2 + 1] * (1.0f / 1024.0f);
    int comp = t >> 6;
    int i = t & 63;
    float dimt = powf(10000.0f, (float)(2 * i) / 64.0f);
    float coord = (comp < 2) ? cx : cy;
    float arg = coord * 6.283185307179586f / dimt;
    float val = (comp & 1) ? cosf(arg) : sinf(arg);
    pe[(size_t)pt * 256 + t] = val;
}

// ---------------- patch gather + 2D DFT + radial binning --------------------
__global__ void __launch_bounds__(256) fft_feat_kernel(const float* __restrict__ image,
                                                       const float* __restrict__ coords,
                                                       const float* __restrict__ fbi,
                                                       float* __restrict__ feat) {
    int pt = blockIdx.x;
    int b = pt >> 9;
    int tid = threadIdx.x;

    __shared__ float patch[16][16];
    __shared__ float Rre[16][9], Rim[16][9];
    __shared__ float twc[16], tws[16];
    __shared__ float bmag[8], bang[8];
    __shared__ int bcnt[8];
    __shared__ float smf[8];
    __shared__ int spx, spy;

    if (tid == 0) {
        float cx = coords[pt * 2];
        float cy = coords[pt * 2 + 1];
        int px = (int)cx; px = min(max(px, 8), 1015);
        int py = (int)cy; py = min(max(py, 8), 1015);
        spx = px; spy = py;
        float mx = -1e30f;
        for (int i = 0; i < 8; i++) mx = fmaxf(mx, fbi[i]);
        float s = 0.0f;
        for (int i = 0; i < 8; i++) { float e = expf(fbi[i] - mx); smf[i] = e; s += e; }
        float inv = 1.0f / s;
        for (int i = 0; i < 8; i++) smf[i] *= inv;
    }
    if (tid < 16) {
        twc[tid] = cospif((float)tid / 8.0f);
        tws[tid] = sinpif(-(float)tid / 8.0f);
    }
    if (tid < 8) { bmag[tid] = 0.0f; bang[tid] = 0.0f; bcnt[tid] = 0; }
    __syncthreads();

    int y = tid >> 4, x = tid & 15;
    int yy = spy - 8 + y, xx = spx - 8 + x;
    const float* imb = image + (size_t)b * 3u * 1024u * 1024u;
    size_t off = (size_t)yy * 1024 + xx;
    float gsum = imb[off] + imb[1048576u + off] + imb[2097152u + off];
    patch[y][x] = gsum * (1.0f / 3.0f);
    __syncthreads();

    if (tid < 144) {
        int ry = tid / 9, kx = tid % 9;
        float re = 0.0f, im = 0.0f;
#pragma unroll
        for (int j = 0; j < 16; j++) {
            float pv = patch[ry][j];
            int t = (kx * j) & 15;
            re += pv * twc[t];
            im += pv * tws[t];
        }
        Rre[ry][kx] = re;
        Rim[ry][kx] = im;
    }
    __syncthreads();

    if (tid < 144) {
        int ky = tid / 9, kx = tid % 9;
        float re = 0.0f, im = 0.0f;
#pragma unroll
        for (int j = 0; j < 16; j++) {
            int t = (ky * j) & 15;
            float c = twc[t], s = tws[t];
            float ar = Rre[j][kx], ai = Rim[j][kx];
            re += ar * c - ai * s;
            im += ar * s + ai * c;
        }
        re *= 0.0625f;
        im *= 0.0625f;
        float mag = sqrtf(re * re + im * im);
        float ang = atan2f(im, re);

        double fy = (ky < 8) ? (double)ky / 16.0 : ((double)ky - 16.0) / 16.0;
        double fx = (double)kx / 16.0;
        double r = sqrt(fx * fx + fy * fy);
        double maxr = 0.7071067811865476 + 1e-6;
        double step = maxr / 8.0;
        int bi = 0;
#pragma unroll
        for (int k = 1; k < 9; k++) if (r >= (double)k * step) bi = k;
        if (bi > 7) bi = 7;
        atomicAdd(&bmag[bi], mag);
        atomicAdd(&bang[bi], ang);
        atomicAdd(&bcnt[bi], 1);
    }
    __syncthreads();

    if (tid < 8) {
        float c = (float)max(bcnt[tid], 1);
        feat[(size_t)pt * 16 + tid]     = bmag[tid] / c * smf[tid];
        feat[(size_t)pt * 16 + 8 + tid] = bang[tid] / c;
    }
}

// ---------------- tiled SGEMM v2: C[M,N] = A[M,K] @ W[N,K]^T + bias ---------
// 64x64 tile, 128 threads, 8x4 microtile, double-buffered smem.
// EP: 0 = bias, 1 = bias+gelu, 2 = bias + type_emb[label[row]]
template <int EP>
__global__ void __launch_bounds__(128) gemm2(const float* __restrict__ A,
                                             const float* __restrict__ W,
                                             const float* __restrict__ bias,
                                             float* __restrict__ C,
                                             int M, int N, int K,
                                             const int* __restrict__ labels,
                                             const float* __restrict__ temb) {
    __shared__ __align__(16) float As[2][16][72];
    __shared__ __align__(16) float Bs[2][16][72];

    const int tid = threadIdx.x;
    const int tx = tid & 15;         // 16 col-groups of 4
    const int ty = tid >> 4;         // 8 row-groups of 8
    const int m0 = blockIdx.y << 6, n0 = blockIdx.x << 6;
    const int lrow = tid >> 1;       // 0..63
    const int lk = (tid & 1) << 3;   // 0 or 8

    const float* Aptr = A + (size_t)(m0 + lrow) * K + lk;
    const float* Wptr = W + (size_t)(n0 + lrow) * K + lk;

    float acc[8][4] = {};

    // preload tile 0
    {
        float4 a0 = *(const float4*)(Aptr);
        float4 a1 = *(const float4*)(Aptr + 4);
        float4 b0 = *(const float4*)(Wptr);
        float4 b1 = *(const float4*)(Wptr + 4);
        As[0][lk + 0][lrow] = a0.x; As[0][lk + 1][lrow] = a0.y;
        As[0][lk + 2][lrow] = a0.z; As[0][lk + 3][lrow] = a0.w;
        As[0][lk + 4][lrow] = a1.x; As[0][lk + 5][lrow] = a1.y;
        As[0][lk + 6][lrow] = a1.z; As[0][lk + 7][lrow] = a1.w;
        Bs[0][lk + 0][lrow] = b0.x; Bs[0][lk + 1][lrow] = b0.y;
        Bs[0][lk + 2][lrow] = b0.z; Bs[0][lk + 3][lrow] = b0.w;
        Bs[0][lk + 4][lrow] = b1.x; Bs[0][lk + 5][lrow] = b1.y;
        Bs[0][lk + 6][lrow] = b1.z; Bs[0][lk + 7][lrow] = b1.w;
    }
    __syncthreads();

    int buf = 0;
    for (int k0 = 0; k0 < K; k0 += 16) {
        const bool notlast = (k0 + 16 < K);
        float4 pa0, pa1, pb0, pb1;
        if (notlast) {
            pa0 = *(const float4*)(Aptr + k0 + 16);
            pa1 = *(const float4*)(Aptr + k0 + 20);
            pb0 = *(const float4*)(Wptr + k0 + 16);
            pb1 = *(const float4*)(Wptr + k0 + 20);
        }
#pragma unroll
        for (int kk = 0; kk < 16; kk++) {
            float4 a0 = *(const float4*)&As[buf][kk][ty << 3];
            float4 a1 = *(const float4*)&As[buf][kk][(ty << 3) + 4];
            float4 b0 = *(const float4*)&Bs[buf][kk][tx << 2];
            float ar[8] = {a0.x, a0.y, a0.z, a0.w, a1.x, a1.y, a1.z, a1.w};
            float br[4] = {b0.x, b0.y, b0.z, b0.w};
#pragma unroll
            for (int i = 0; i < 8; i++)
#pragma unroll
                for (int j = 0; j < 4; j++)
                    acc[i][j] += ar[i] * br[j];
        }
        if (notlast) {
            int nb = buf ^ 1;
            As[nb][lk + 0][lrow] = pa0.x; As[nb][lk + 1][lrow] = pa0.y;
            As[nb][lk + 2][lrow] = pa0.z; As[nb][lk + 3][lrow] = pa0.w;
            As[nb][lk + 4][lrow] = pa1.x; As[nb][lk + 5][lrow] = pa1.y;
            As[nb][lk + 6][lrow] = pa1.z; As[nb][lk + 7][lrow] = pa1.w;
            Bs[nb][lk + 0][lrow] = pb0.x; Bs[nb][lk + 1][lrow] = pb0.y;
            Bs[nb][lk + 2][lrow] = pb0.z; Bs[nb][lk + 3][lrow] = pb0.w;
            Bs[nb][lk + 4][lrow] = pb1.x; Bs[nb][lk + 5][lrow] = pb1.y;
            Bs[nb][lk + 6][lrow] = pb1.z; Bs[nb][lk + 7][lrow] = pb1.w;
            __syncthreads();
            buf = nb;
        }
    }

    float4 bb = *(const float4*)(bias + n0 + (tx << 2));
#pragma unroll
    for (int i = 0; i < 8; i++) {
        int row = m0 + (ty << 3) + i;
        float4 o;
        o.x = acc[i][0] + bb.x; o.y = acc[i][1] + bb.y;
        o.z = acc[i][2] + bb.z; o.w = acc[i][3] + bb.w;
        if (EP == 1) {
            o.x = gelu_f(o.x); o.y = gelu_f(o.y);
            o.z = gelu_f(o.z); o.w = gelu_f(o.w);
        }
        if (EP == 2) {
            const float* trow = temb + (size_t)labels[row] * 256 + n0 + (tx << 2);
            float4 t4 = *(const float4*)trow;
            o.x += t4.x; o.y += t4.y; o.z += t4.z; o.w += t4.w;
        }
        *(float4*)(C + (size_t)row * N + n0 + (tx << 2)) = o;
    }
}

// ---------------- layer norm ------------------------------------------------
template <int WIDTH, bool GELU, bool RES>
__global__ void __launch_bounds__(WIDTH) ln_kernel(const float* __restrict__ in,
                                                   const float* __restrict__ res,
                                                   const float* __restrict__ g,
                                                   const float* __restrict__ bv,
                                                   float* __restrict__ out) {
    __shared__ float sh[32];
    int row = blockIdx.x, t = threadIdx.x;
    float v = in[(size_t)row * WIDTH + t];
    if (RES) v += res[(size_t)row * WIDTH + t];
    float s = blockReduceSum(v, sh);
    float mean = s * (1.0f / WIDTH);
    float d = v - mean;
    float s2 = blockReduceSum(d * d, sh);
    float var = s2 * (1.0f / WIDTH);
    float o = g[t] * d * rsqrtf(var + 1e-5f) + bv[t];
    if (GELU) o = gelu_f(o);
    out[(size_t)row * WIDTH + t] = o;
}

// ---------------- attention: block per (b, h, 16-q tile) --------------------
// K/V come interleaved from g_kv (row stride 512, V at +256).
__global__ void __launch_bounds__(256) attn_kernel(const float* __restrict__ Q,
                                                   const float* __restrict__ KV,
                                                   float* __restrict__ O) {
    __shared__ __align__(16) float Qs[16][64];
    __shared__ __align__(16) float Ks[32][64];
    __shared__ float S[16][512];
    __shared__ float rs[16];
    int b = blockIdx.z, h = blockIdx.y, q0 = blockIdx.x << 4;
    int tid = threadIdx.x;
    size_t baseQ = ((size_t)(b * 512 + q0)) * 256 + h * 64;
    const float* Kbase = KV + (size_t)b * 512 * 512 + h * 64;
    const float* Vbase = Kbase + 256;

    {
        int qi = tid >> 4, dg = (tid & 15) << 2;
        *(float4*)&Qs[qi][dg] = *(const float4*)(Q + baseQ + (size_t)qi * 256 + dg);
    }

    for (int kc = 0; kc < 512; kc += 32) {
        __syncthreads();
#pragma unroll
        for (int r = 0; r < 2; r++) {
            int idx = tid + (r << 8);
            int ki = idx >> 4, dg = (idx & 15) << 2;
            *(float4*)&Ks[ki][dg] =
                *(const float4*)(Kbase + (size_t)(kc + ki) * 512 + dg);
        }
        __syncthreads();
#pragma unroll
        for (int r = 0; r < 2; r++) {
            int idx = tid + (r << 8);
            int qi = idx >> 5, ki = idx & 31;
            float s = 0.0f;
#pragma unroll
            for (int d = 0; d < 64; d += 4) {
                float4 qa = *(const float4*)&Qs[qi][d];
                float4 kb = *(const float4*)&Ks[ki][d];
                s += qa.x * kb.x + qa.y * kb.y + qa.z * kb.z + qa.w * kb.w;
            }
            S[qi][kc + ki] = s * 0.125f;
        }
    }
    __syncthreads();

    {
        int w = tid >> 5, lane = tid & 31;
        for (int r = w * 2; r < w * 2 + 2; r++) {
            float m = -1e30f;
            for (int j = lane; j < 512; j += 32) m = fmaxf(m, S[r][j]);
#pragma unroll
            for (int o = 16; o; o >>= 1) m = fmaxf(m, __shfl_xor_sync(0xffffffffu, m, o));
            float sum = 0.0f;
            for (int j = lane; j < 512; j += 32) {
                float e = expf(S[r][j] - m);
                S[r][j] = e;
                sum += e;
            }
#pragma unroll
            for (int o = 16; o; o >>= 1) sum += __shfl_xor_sync(0xffffffffu, sum, o);
            if (lane == 0) rs[r] = sum;
        }
    }
    __syncthreads();

    int qi = tid >> 4, d0 = (tid & 15) << 2;
    float acc0 = 0, acc1 = 0, acc2 = 0, acc3 = 0;
    for (int kc = 0; kc < 512; kc += 32) {
        __syncthreads();
#pragma unroll
        for (int r = 0; r < 2; r++) {
            int idx = tid + (r << 8);
            int ki = idx >> 4, dg = (idx & 15) << 2;
            *(float4*)&Ks[ki][dg] =
                *(const float4*)(Vbase + (size_t)(kc + ki) * 512 + dg);
        }
        __syncthreads();
#pragma unroll
        for (int ki = 0; ki < 32; ki++) {
            float p = S[qi][kc + ki];
            float4 vv = *(const float4*)&Ks[ki][d0];
            acc0 += p * vv.x; acc1 += p * vv.y; acc2 += p * vv.z; acc3 += p * vv.w;
        }
    }
    float inv = 1.0f / rs[qi];
    float4 o4;
    o4.x = acc0 * inv; o4.y = acc1 * inv; o4.z = acc2 * inv; o4.w = acc3 * inv;
    *(float4*)(O + baseQ + (size_t)qi * 256 + d0) = o4;
}

// ---------------- launch ----------------------------------------------------
extern "C" void kernel_launch(void* const* d_in, const int* in_sizes, int n_in,
                              void* d_out, int out_size) {
    (void)in_sizes; (void)n_in; (void)out_size;
    const float* image  = (const float*)d_in[0];
    const float* coords = (const float*)d_in[1];
    const int*   labels = (const int*)d_in[2];
    const float* pe_w   = (const float*)d_in[3];
    const float* pe_b   = (const float*)d_in[4];
    const float* temb   = (const float*)d_in[5];
    const float* fbi    = (const float*)d_in[6];
    const float* fe1_w  = (const float*)d_in[7];
    const float* fe1_b  = (const float*)d_in[8];
    const float* feln1g = (const float*)d_in[9];
    const float* feln1b = (const float*)d_in[10];
    const float* fe2_w  = (const float*)d_in[11];
    const float* fe2_b  = (const float*)d_in[12];
    const float* feln2g = (const float*)d_in[13];
    const float* feln2b = (const float*)d_in[14];
    const float* in_w   = (const float*)d_in[15];
    const float* in_b   = (const float*)d_in[16];
    const float* ao_w   = (const float*)d_in[17];
    const float* ao_b   = (const float*)d_in[18];
    const float* n1_g   = (const float*)d_in[19];
    const float* n1_b   = (const float*)d_in[20];
    const float* f1_w   = (const float*)d_in[21];
    const float* f1_b   = (const float*)d_in[22];
    const float* f2_w   = (const float*)d_in[23];
    const float* f2_b   = (const float*)d_in[24];
    const float* n2_g   = (const float*)d_in[25];
    const float* n2_b   = (const float*)d_in[26];
    const float* op_w   = (const float*)d_in[27];
    const float* op_b   = (const float*)d_in[28];
    float* out = (float*)d_out;

    float *p_pe, *p_spatial, *p_feat, *p_fe1, *p_h1, *p_fe2, *p_freq;
    float *p_q, *p_kv, *p_o, *p_ao, *p_x, *p_ffh, *p_ff2, *p_x2;
    cudaGetSymbolAddress((void**)&p_pe, g_pe);
    cudaGetSymbolAddress((void**)&p_spatial, g_spatial);
    cudaGetSymbolAddress((void**)&p_feat, g_feat);
    cudaGetSymbolAddress((void**)&p_fe1, g_fe1);
    cudaGetSymbolAddress((void**)&p_h1, g_h1);
    cudaGetSymbolAddress((void**)&p_fe2, g_fe2);
    cudaGetSymbolAddress((void**)&p_freq, g_freq);
    cudaGetSymbolAddress((void**)&p_q, g_q);
    cudaGetSymbolAddress((void**)&p_kv, g_kv);
    cudaGetSymbolAddress((void**)&p_o, g_o);
    cudaGetSymbolAddress((void**)&p_ao, g_ao);
    cudaGetSymbolAddress((void**)&p_x, g_x);
    cudaGetSymbolAddress((void**)&p_ffh, g_ffh);
    cudaGetSymbolAddress((void**)&p_ff2, g_ff2);
    cudaGetSymbolAddress((void**)&p_x2, g_x2);

    // 1) sinusoidal PE
    pe_kernel<<<PTS, 256>>>(coords, p_pe);
    // 2) spatial = PE @ pe_w^T + pe_b + type_emb[label]
    gemm2<2><<<dim3(4, 64), 128>>>(p_pe, pe_w, pe_b, p_spatial, PTS, 256, 256, labels, temb);
    // 3) patch FFT features
    fft_feat_kernel<<<PTS, 256>>>(image, coords, fbi, p_feat);
    // 4) freq MLP
    gemm2<0><<<dim3(2, 64), 128>>>(p_feat, fe1_w, fe1_b, p_fe1, PTS, 128, 16, nullptr, nullptr);
    ln_kernel<128, true, false><<<PTS, 128>>>(p_fe1, nullptr, feln1g, feln1b, p_h1);
    gemm2<0><<<dim3(4, 64), 128>>>(p_h1, fe2_w, fe2_b, p_fe2, PTS, 256, 128, nullptr, nullptr);
    ln_kernel<256, false, false><<<PTS, 256>>>(p_fe2, nullptr, feln2g, feln2b, p_freq);
    // 5) Q projection + fused K/V projection (N=512)
    gemm2<0><<<dim3(4, 64), 128>>>(p_spatial, in_w,             in_b,       p_q,  PTS, 256, 256, nullptr, nullptr);
    gemm2<0><<<dim3(8, 64), 128>>>(p_freq,    in_w + 256 * 256, in_b + 256, p_kv, PTS, 512, 256, nullptr, nullptr);
    // 6) attention
    attn_kernel<<<dim3(32, 4, 8), 256>>>(p_q, p_kv, p_o);
    // 7) attn out proj + residual LN
    gemm2<0><<<dim3(4, 64), 128>>>(p_o, ao_w, ao_b, p_ao, PTS, 256, 256, nullptr, nullptr);
    ln_kernel<256, false, true><<<PTS, 256>>>(p_ao, p_spatial, n1_g, n1_b, p_x);
    // 8) FFN
    gemm2<1><<<dim3(8, 64), 128>>>(p_x, f1_w, f1_b, p_ffh, PTS, 512, 256, nullptr, nullptr);
    gemm2<0><<<dim3(4, 64), 128>>>(p_ffh, f2_w, f2_b, p_ff2, PTS, 256, 512, nullptr, nullptr);
    ln_kernel<256, false, true><<<PTS, 256>>>(p_ff2, p_x, n2_g, n2_b, p_x2);
    // 9) output projection
    gemm2<0><<<dim3(4, 64), 128>>>(p_x2, op_w, op_b, out, PTS, 256, 256, nullptr, nullptr);
}

// round 4
// speedup vs baseline: 1.1080x; 1.0411x over previous
#include <cuda_runtime.h>
#include <math.h>

#define PTS 4096      // B*N = 8*512

// ---------------- scratch (device globals) ----------------------------------
__device__ float g_pe[PTS * 256];
__device__ float g_spatial[PTS * 256];
__device__ float g_feat[PTS * 16];
__device__ float g_fe1[PTS * 128];
__device__ float g_h1[PTS * 128];
__device__ float g_fe2[PTS * 256];
__device__ float g_freq[PTS * 256];
__device__ float g_q[PTS * 256];
__device__ float g_kv[PTS * 512];
__device__ float g_S[32u * 512u * 512u];   // attention scores, 33.5 MB
__device__ float g_o[PTS * 256];
__device__ float g_ao[PTS * 256];
__device__ float g_x[PTS * 256];
__device__ float g_ffh[PTS * 512];
__device__ float g_ff2[PTS * 256];
__device__ float g_x2[PTS * 256];

__device__ __forceinline__ float gelu_f(float x) {
    return 0.5f * x * (1.0f + erff(x * 0.7071067811865475f));
}

// ---------------- PE kernel: 128 threads/point, sincos pairs ----------------
__global__ void __launch_bounds__(128) pe_kernel(const float* __restrict__ coords,
                                                 float* __restrict__ pe) {
    int pt = blockIdx.x, t = threadIdx.x;
    int i = t & 63, comp = t >> 6;            // comp 0 = x, 1 = y
    float c = coords[pt * 2 + comp] * (1.0f / 1024.0f);
    // 1/dim_t = 10000^(-i/32) = exp2(-i * log2(10000)/32)
    float arg = c * 6.283185307179586f * exp2f(-(float)i * 0.4152410118609203f);
    float s, co;
    sincosf(arg, &s, &co);
    size_t base = (size_t)pt * 256 + (comp << 7) + i;
    pe[base] = s;
    pe[base + 64] = co;
}

// ---------------- patch gather + 2D DFT + radial binning --------------------
__global__ void __launch_bounds__(256) fft_feat_kernel(const float* __restrict__ image,
                                                       const float* __restrict__ coords,
                                                       const float* __restrict__ fbi,
                                                       float* __restrict__ feat) {
    int pt = blockIdx.x;
    int b = pt >> 9;
    int tid = threadIdx.x;

    __shared__ float patch[16][16];
    __shared__ float Rre[16][9], Rim[16][9];
    __shared__ float twc[16], tws[16];
    __shared__ float bmag[8], bang[8];
    __shared__ int bcnt[8];
    __shared__ float smf[8];
    __shared__ int spx, spy;

    if (tid == 0) {
        float cx = coords[pt * 2];
        float cy = coords[pt * 2 + 1];
        int px = (int)cx; px = min(max(px, 8), 1015);
        int py = (int)cy; py = min(max(py, 8), 1015);
        spx = px; spy = py;
        float mx = -1e30f;
        for (int i = 0; i < 8; i++) mx = fmaxf(mx, fbi[i]);
        float s = 0.0f;
        for (int i = 0; i < 8; i++) { float e = expf(fbi[i] - mx); smf[i] = e; s += e; }
        float inv = 1.0f / s;
        for (int i = 0; i < 8; i++) smf[i] *= inv;
    }
    if (tid < 16) {
        twc[tid] = cospif((float)tid / 8.0f);
        tws[tid] = sinpif(-(float)tid / 8.0f);
    }
    if (tid < 8) { bmag[tid] = 0.0f; bang[tid] = 0.0f; bcnt[tid] = 0; }
    __syncthreads();

    int y = tid >> 4, x = tid & 15;
    int yy = spy - 8 + y, xx = spx - 8 + x;
    const float* imb = image + (size_t)b * 3u * 1024u * 1024u;
    size_t off = (size_t)yy * 1024 + xx;
    float gsum = imb[off] + imb[1048576u + off] + imb[2097152u + off];
    patch[y][x] = gsum * (1.0f / 3.0f);
    __syncthreads();

    if (tid < 144) {
        int ry = tid / 9, kx = tid % 9;
        float re = 0.0f, im = 0.0f;
#pragma unroll
        for (int j = 0; j < 16; j++) {
            float pv = patch[ry][j];
            int t = (kx * j) & 15;
            re += pv * twc[t];
            im += pv * tws[t];
        }
        Rre[ry][kx] = re;
        Rim[ry][kx] = im;
    }
    __syncthreads();

    if (tid < 144) {
        int ky = tid / 9, kx = tid % 9;
        float re = 0.0f, im = 0.0f;
#pragma unroll
        for (int j = 0; j < 16; j++) {
            int t = (ky * j) & 15;
            float c = twc[t], s = tws[t];
            float ar = Rre[j][kx], ai = Rim[j][kx];
            re += ar * c - ai * s;
            im += ar * s + ai * c;
        }
        re *= 0.0625f;
        im *= 0.0625f;
        float mag = sqrtf(re * re + im * im);
        float ang = atan2f(im, re);

        double fy = (ky < 8) ? (double)ky / 16.0 : ((double)ky - 16.0) / 16.0;
        double fx = (double)kx / 16.0;
        double r = sqrt(fx * fx + fy * fy);
        double maxr = 0.7071067811865476 + 1e-6;
        double step = maxr / 8.0;
        int bi = 0;
#pragma unroll
        for (int k = 1; k < 9; k++) if (r >= (double)k * step) bi = k;
        if (bi > 7) bi = 7;
        atomicAdd(&bmag[bi], mag);
        atomicAdd(&bang[bi], ang);
        atomicAdd(&bcnt[bi], 1);
    }
    __syncthreads();

    if (tid < 8) {
        float c = (float)max(bcnt[tid], 1);
        feat[(size_t)pt * 16 + tid]     = bmag[tid] / c * smf[tid];
        feat[(size_t)pt * 16 + 8 + tid] = bang[tid] / c;
    }
}

// ---------------- GEMM v3: 32x64 tile, 128 threads, 4x4 microtile -----------
// C = A @ B(^T) ; BT=false: B is [N,K] row-major (W^T form). BT=true: B is [K,N].
// Batched over blockIdx.z via (b = z>>2, h = z&3) stride pairs.
// EP: 0 bias, 1 bias+gelu, 2 bias+type_emb, 3 alpha-scale only (no bias).
template <int EP, bool BT>
__global__ void __launch_bounds__(128) gemm3(
    const float* __restrict__ A, const float* __restrict__ B,
    const float* __restrict__ bias, float* __restrict__ C,
    int K, int lda, int ldb, int ldc,
    size_t sAb, size_t sAh, size_t sBb, size_t sBh, size_t sCb, size_t sCh,
    float alpha, const int* __restrict__ labels, const float* __restrict__ temb)
{
    __shared__ __align__(16) float As[2][16][36];
    __shared__ __align__(16) float Bs[2][16][68];

    const int z = blockIdx.z;
    A += (size_t)(z >> 2) * sAb + (size_t)(z & 3) * sAh;
    B += (size_t)(z >> 2) * sBb + (size_t)(z & 3) * sBh;
    C += (size_t)(z >> 2) * sCb + (size_t)(z & 3) * sCh;

    const int tid = threadIdx.x;
    const int tx = tid & 15, ty = tid >> 4;
    const int m0 = blockIdx.y << 5, n0 = blockIdx.x << 6;

    const int arow = tid >> 2, ak = (tid & 3) << 2;       // A: 32 rows x 16 k
    const float* Aptr = A + (size_t)(m0 + arow) * lda + ak;

    // B pointers for the two layouts
    const int brow = tid >> 1, bk = (tid & 1) << 3;       // NK: 64 rows x 16 k
    const int krow = tid >> 3, nc = (tid & 7) << 3;       // KN: 16 k x 64 n
    const float* Bptr = BT ? (B + (size_t)krow * ldb + n0 + nc)
                           : (B + (size_t)(n0 + brow) * ldb + bk);

    float acc[4][4] = {};

    // preload tile 0
    {
        float4 av = *(const float4*)Aptr;
        As[0][ak + 0][arow] = av.x; As[0][ak + 1][arow] = av.y;
        As[0][ak + 2][arow] = av.z; As[0][ak + 3][arow] = av.w;
        if (!BT) {
            float4 b0 = *(const float4*)Bptr;
            float4 b1 = *(const float4*)(Bptr + 4);
            Bs[0][bk + 0][brow] = b0.x; Bs[0][bk + 1][brow] = b0.y;
            Bs[0][bk + 2][brow] = b0.z; Bs[0][bk + 3][brow] = b0.w;
            Bs[0][bk + 4][brow] = b1.x; Bs[0][bk + 5][brow] = b1.y;
            Bs[0][bk + 6][brow] = b1.z; Bs[0][bk + 7][brow] = b1.w;
        } else {
            *(float4*)&Bs[0][krow][nc]     = *(const float4*)Bptr;
            *(float4*)&Bs[0][krow][nc + 4] = *(const float4*)(Bptr + 4);
        }
    }
    __syncthreads();

    int buf = 0;
    for (int k0 = 0; k0 < K; k0 += 16) {
        const bool notlast = (k0 + 16 < K);
        float4 pa, pb0, pb1;
        if (notlast) {
            pa = *(const float4*)(Aptr + k0 + 16);
            if (!BT) {
                pb0 = *(const float4*)(Bptr + k0 + 16);
                pb1 = *(const float4*)(Bptr + k0 + 20);
            } else {
                const float* bp = Bptr + (size_t)(k0 + 16) * ldb;
                pb0 = *(const float4*)bp;
                pb1 = *(const float4*)(bp + 4);
            }
        }
#pragma unroll
        for (int kk = 0; kk < 16; kk++) {
            float4 a4 = *(const float4*)&As[buf][kk][ty << 2];
            float4 b4 = *(const float4*)&Bs[buf][kk][tx << 2];
            float ar[4] = {a4.x, a4.y, a4.z, a4.w};
            float br[4] = {b4.x, b4.y, b4.z, b4.w};
#pragma unroll
            for (int i = 0; i < 4; i++)
#pragma unroll
                for (int j = 0; j < 4; j++)
                    acc[i][j] += ar[i] * br[j];
        }
        if (notlast) {
            int nb = buf ^ 1;
            As[nb][ak + 0][arow] = pa.x; As[nb][ak + 1][arow] = pa.y;
            As[nb][ak + 2][arow] = pa.z; As[nb][ak + 3][arow] = pa.w;
            if (!BT) {
                Bs[nb][bk + 0][brow] = pb0.x; Bs[nb][bk + 1][brow] = pb0.y;
                Bs[nb][bk + 2][brow] = pb0.z; Bs[nb][bk + 3][brow] = pb0.w;
                Bs[nb][bk + 4][brow] = pb1.x; Bs[nb][bk + 5][brow] = pb1.y;
                Bs[nb][bk + 6][brow] = pb1.z; Bs[nb][bk + 7][brow] = pb1.w;
            } else {
                *(float4*)&Bs[nb][krow][nc]     = pb0;
                *(float4*)&Bs[nb][krow][nc + 4] = pb1;
            }
            __syncthreads();
            buf = nb;
        }
    }

    float4 bb = make_float4(0.f, 0.f, 0.f, 0.f);
    if (EP != 3) bb = *(const float4*)(bias + n0 + (tx << 2));
#pragma unroll
    for (int i = 0; i < 4; i++) {
        int row = m0 + (ty << 2) + i;
        float4 o;
        o.x = acc[i][0]; o.y = acc[i][1]; o.z = acc[i][2]; o.w = acc[i][3];
        if (EP == 3) {
            o.x *= alpha; o.y *= alpha; o.z *= alpha; o.w *= alpha;
        } else {
            o.x += bb.x; o.y += bb.y; o.z += bb.z; o.w += bb.w;
        }
        if (EP == 1) {
            o.x = gelu_f(o.x); o.y = gelu_f(o.y);
            o.z = gelu_f(o.z); o.w = gelu_f(o.w);
        }
        if (EP == 2) {
            const float* trow = temb + (size_t)labels[row] * 256 + n0 + (tx << 2);
            float4 t4 = *(const float4*)trow;
            o.x += t4.x; o.y += t4.y; o.z += t4.z; o.w += t4.w;
        }
        *(float4*)(C + (size_t)row * ldc + n0 + (tx << 2)) = o;
    }
}

// ---------------- softmax over 512-wide rows (in place) ---------------------
__global__ void __launch_bounds__(128) softmax512(float* __restrict__ S) {
    __shared__ float sh[4];
    size_t row = blockIdx.x;
    float4* p = (float4*)(S + row * 512);
    int t = threadIdx.x;
    float4 v = p[t];
    float m = fmaxf(fmaxf(v.x, v.y), fmaxf(v.z, v.w));
#pragma unroll
    for (int o = 16; o; o >>= 1) m = fmaxf(m, __shfl_xor_sync(0xffffffffu, m, o));
    if ((t & 31) == 0) sh[t >> 5] = m;
    __syncthreads();
    m = fmaxf(fmaxf(sh[0], sh[1]), fmaxf(sh[2], sh[3]));
    v.x = expf(v.x - m); v.y = expf(v.y - m);
    v.z = expf(v.z - m); v.w = expf(v.w - m);
    float s = v.x + v.y + v.z + v.w;
#pragma unroll
    for (int o = 16; o; o >>= 1) s += __shfl_xor_sync(0xffffffffu, s, o);
    __syncthreads();
    if ((t & 31) == 0) sh[t >> 5] = s;
    __syncthreads();
    s = sh[0] + sh[1] + sh[2] + sh[3];
    float inv = 1.0f / s;
    v.x *= inv; v.y *= inv; v.z *= inv; v.w *= inv;
    p[t] = v;
}

// ---------------- layer norm: warp per row ----------------------------------
template <int WIDTH, bool GELU, bool RES>
__global__ void __launch_bounds__(128) ln_warp(const float* __restrict__ in,
                                               const float* __restrict__ res,
                                               const float* __restrict__ g,
                                               const float* __restrict__ bv,
                                               float* __restrict__ out) {
    const int V4 = WIDTH / 128;       // float4s per lane (1 or 2)
    int w = threadIdx.x >> 5, lane = threadIdx.x & 31;
    int row = (blockIdx.x << 2) + w;
    const float4* ip = (const float4*)(in + (size_t)row * WIDTH);
    const float4* rp = (const float4*)(res + (size_t)row * WIDTH);
    float4 v[V4];
    float s = 0.0f;
#pragma unroll
    for (int i = 0; i < V4; i++) {
        v[i] = ip[lane + 32 * i];
        if (RES) {
            float4 r = rp[lane + 32 * i];
            v[i].x += r.x; v[i].y += r.y; v[i].z += r.z; v[i].w += r.w;
        }
        s += v[i].x + v[i].y + v[i].z + v[i].w;
    }
#pragma unroll
    for (int o = 16; o; o >>= 1) s += __shfl_xor_sync(0xffffffffu, s, o);
    float mean = s * (1.0f / WIDTH);
    float q = 0.0f;
#pragma unroll
    for (int i = 0; i < V4; i++) {
        v[i].x -= mean; v[i].y -= mean; v[i].z -= mean; v[i].w -= mean;
        q += v[i].x * v[i].x + v[i].y * v[i].y + v[i].z * v[i].z + v[i].w * v[i].w;
    }
#pragma unroll
    for (int o = 16; o; o >>= 1) q += __shfl_xor_sync(0xffffffffu, q, o);
    float inv = rsqrtf(q * (1.0f / WIDTH) + 1e-5f);
    const float4* gp = (const float4*)g;
    const float4* bp = (const float4*)bv;
    float4* op = (float4*)(out + (size_t)row * WIDTH);
#pragma unroll
    for (int i = 0; i < V4; i++) {
        float4 gg = gp[lane + 32 * i], bb = bp[lane + 32 * i];
        float4 o;
        o.x = gg.x * v[i].x * inv + bb.x;
        o.y = gg.y * v[i].y * inv + bb.y;
        o.z = gg.z * v[i].z * inv + bb.z;
        o.w = gg.w * v[i].w * inv + bb.w;
        if (GELU) {
            o.x = gelu_f(o.x); o.y = gelu_f(o.y);
            o.z = gelu_f(o.z); o.w = gelu_f(o.w);
        }
        op[lane + 32 * i] = o;
    }
}

// ---------------- launch ----------------------------------------------------
extern "C" void kernel_launch(void* const* d_in, const int* in_sizes, int n_in,
                              void* d_out, int out_size) {
    (void)in_sizes; (void)n_in; (void)out_size;
    const float* image  = (const float*)d_in[0];
    const float* coords = (const float*)d_in[1];
    const int*   labels = (const int*)d_in[2];
    const float* pe_w   = (const float*)d_in[3];
    const float* pe_b   = (const float*)d_in[4];
    const float* temb   = (const float*)d_in[5];
    const float* fbi    = (const float*)d_in[6];
    const float* fe1_w  = (const float*)d_in[7];
    const float* fe1_b  = (const float*)d_in[8];
    const float* feln1g = (const float*)d_in[9];
    const float* feln1b = (const float*)d_in[10];
    const float* fe2_w  = (const float*)d_in[11];
    const float* fe2_b  = (const float*)d_in[12];
    const float* feln2g = (const float*)d_in[13];
    const float* feln2b = (const float*)d_in[14];
    const float* in_w   = (const float*)d_in[15];
    const float* in_b   = (const float*)d_in[16];
    const float* ao_w   = (const float*)d_in[17];
    const float* ao_b   = (const float*)d_in[18];
    const float* n1_g   = (const float*)d_in[19];
    const float* n1_b   = (const float*)d_in[20];
    const float* f1_w   = (const float*)d_in[21];
    const float* f1_b   = (const float*)d_in[22];
    const float* f2_w   = (const float*)d_in[23];
    const float* f2_b   = (const float*)d_in[24];
    const float* n2_g   = (const float*)d_in[25];
    const float* n2_b   = (const float*)d_in[26];
    const float* op_w   = (const float*)d_in[27];
    const float* op_b   = (const float*)d_in[28];
    float* out = (float*)d_out;

    float *p_pe, *p_spatial, *p_feat, *p_fe1, *p_h1, *p_fe2, *p_freq;
    float *p_q, *p_kv, *p_S, *p_o, *p_ao, *p_x, *p_ffh, *p_ff2, *p_x2;
    cudaGetSymbolAddress((void**)&p_pe, g_pe);
    cudaGetSymbolAddress((void**)&p_spatial, g_spatial);
    cudaGetSymbolAddress((void**)&p_feat, g_feat);
    cudaGetSymbolAddress((void**)&p_fe1, g_fe1);
    cudaGetSymbolAddress((void**)&p_h1, g_h1);
    cudaGetSymbolAddress((void**)&p_fe2, g_fe2);
    cudaGetSymbolAddress((void**)&p_freq, g_freq);
    cudaGetSymbolAddress((void**)&p_q, g_q);
    cudaGetSymbolAddress((void**)&p_kv, g_kv);
    cudaGetSymbolAddress((void**)&p_S, g_S);
    cudaGetSymbolAddress((void**)&p_o, g_o);
    cudaGetSymbolAddress((void**)&p_ao, g_ao);
    cudaGetSymbolAddress((void**)&p_x, g_x);
    cudaGetSymbolAddress((void**)&p_ffh, g_ffh);
    cudaGetSymbolAddress((void**)&p_ff2, g_ff2);
    cudaGetSymbolAddress((void**)&p_x2, g_x2);

    const size_t Z = 0;

    // 1) sinusoidal PE
    pe_kernel<<<PTS, 128>>>(coords, p_pe);
    // 2) spatial = PE @ pe_w^T + pe_b + type_emb[label]
    gemm3<2, false><<<dim3(4, 128, 1), 128>>>(p_pe, pe_w, pe_b, p_spatial,
        256, 256, 256, 256, Z, Z, Z, Z, Z, Z, 1.0f, labels, temb);
    // 3) patch FFT features
    fft_feat_kernel<<<PTS, 256>>>(image, coords, fbi, p_feat);
    // 4) freq MLP
    gemm3<0, false><<<dim3(2, 128, 1), 128>>>(p_feat, fe1_w, fe1_b, p_fe1,
        16, 16, 16, 128, Z, Z, Z, Z, Z, Z, 1.0f, nullptr, nullptr);
    ln_warp<128, true, false><<<PTS / 4, 128>>>(p_fe1, p_fe1, feln1g, feln1b, p_h1);
    gemm3<0, false><<<dim3(4, 128, 1), 128>>>(p_h1, fe2_w, fe2_b, p_fe2,
        128, 128, 128, 256, Z, Z, Z, Z, Z, Z, 1.0f, nullptr, nullptr);
    ln_warp<256, false, false><<<PTS / 4, 128>>>(p_fe2, p_fe2, feln2g, feln2b, p_freq);
    // 5) Q projection + fused K/V projection
    gemm3<0, false><<<dim3(4, 128, 1), 128>>>(p_spatial, in_w, in_b, p_q,
        256, 256, 256, 256, Z, Z, Z, Z, Z, Z, 1.0f, nullptr, nullptr);
    gemm3<0, false><<<dim3(8, 128, 1), 128>>>(p_freq, in_w + 65536, in_b + 256, p_kv,
        256, 256, 256, 512, Z, Z, Z, Z, Z, Z, 1.0f, nullptr, nullptr);
    // 6) attention: S = Q K^T / 8, softmax, O = P V
    gemm3<3, false><<<dim3(8, 16, 32), 128>>>(p_q, p_kv, nullptr, p_S,
        64, 256, 512, 512,
        (size_t)131072, (size_t)64, (size_t)262144, (size_t)64,
        (size_t)1048576, (size_t)262144, 0.125f, nullptr, nullptr);
    softmax512<<<32 * 512, 128>>>(p_S);
    gemm3<3, true><<<dim3(1, 16, 32), 128>>>(p_S, p_kv + 256, nullptr, p_o,
        512, 512, 512, 256,
        (size_t)1048576, (size_t)262144, (size_t)262144, (size_t)64,
        (size_t)131072, (size_t)64, 1.0f, nullptr, nullptr);
    // 7) attn out proj + residual LN
    gemm3<0, false><<<dim3(4, 128, 1), 128>>>(p_o, ao_w, ao_b, p_ao,
        256, 256, 256, 256, Z, Z, Z, Z, Z, Z, 1.0f, nullptr, nullptr);
    ln_warp<256, false, true><<<PTS / 4, 128>>>(p_ao, p_spatial, n1_g, n1_b, p_x);
    // 8) FFN
    gemm3<1, false><<<dim3(8, 128, 1), 128>>>(p_x, f1_w, f1_b, p_ffh,
        256, 256, 256, 512, Z, Z, Z, Z, Z, Z, 1.0f, nullptr, nullptr);
    gemm3<0, false><<<dim3(4, 128, 1), 128>>>(p_ffh, f2_w, f2_b, p_ff2,
        512, 512, 512, 256, Z, Z, Z, Z, Z, Z, 1.0f, nullptr, nullptr);
    ln_warp<256, false, true><<<PTS / 4, 128>>>(p_ff2, p_x, n2_g, n2_b, p_x2);
    // 9) output projection
    gemm3<0, false><<<dim3(4, 128, 1), 128>>>(p_x2, op_w, op_b, out,
        256, 256, 256, 256, Z, Z, Z, Z, Z, Z, 1.0f, nullptr, nullptr);
}

// round 5
// speedup vs baseline: 2.1961x; 1.9820x over previous
#include <cuda_runtime.h>
#include <math.h>

#define PTS 4096      // B*N = 8*512

// ---------------- scratch (device globals) ----------------------------------
__device__ float g_pe[PTS * 256];
__device__ float g_spatial[PTS * 256];
__device__ float g_feat[PTS * 16];
__device__ float g_fe1[PTS * 128];
__device__ float g_h1[PTS * 128];
__device__ float g_fe2[PTS * 256];
__device__ float g_freq[PTS * 256];
__device__ float g_q[PTS * 256];
__device__ float g_kv[PTS * 512];
__device__ float g_S[32u * 512u * 512u];   // attention scores, 33.5 MB
__device__ float g_o[PTS * 256];
__device__ float g_ao[PTS * 256];
__device__ float g_x[PTS * 256];
__device__ float g_ffh[PTS * 512];
__device__ float g_ff2[PTS * 256];
__device__ float g_x2[PTS * 256];

__device__ __forceinline__ float gelu_f(float x) {
    return 0.5f * x * (1.0f + erff(x * 0.7071067811865475f));
}

// tf32 helpers ---------------------------------------------------------------
__device__ __forceinline__ unsigned tf32_rna(float x) {
    unsigned r;
    asm("cvt.rna.tf32.f32 %0, %1;" : "=r"(r) : "f"(x));
    return r;
}
__device__ __forceinline__ void mma8(float* c, unsigned a0, unsigned a1,
                                     unsigned a2, unsigned a3,
                                     unsigned b0, unsigned b1) {
    asm("mma.sync.aligned.m16n8k8.row.col.f32.tf32.tf32.f32 "
        "{%0,%1,%2,%3},{%4,%5,%6,%7},{%8,%9},{%0,%1,%2,%3};"
        : "+f"(c[0]), "+f"(c[1]), "+f"(c[2]), "+f"(c[3])
        : "r"(a0), "r"(a1), "r"(a2), "r"(a3), "r"(b0), "r"(b1));
}

// ---------------- PE kernel -------------------------------------------------
__global__ void __launch_bounds__(128) pe_kernel(const float* __restrict__ coords,
                                                 float* __restrict__ pe) {
    int pt = blockIdx.x, t = threadIdx.x;
    int i = t & 63, comp = t >> 6;
    float c = coords[pt * 2 + comp] * (1.0f / 1024.0f);
    float arg = c * 6.283185307179586f * exp2f(-(float)i * 0.4152410118609203f);
    float s, co;
    sincosf(arg, &s, &co);
    size_t base = (size_t)pt * 256 + (comp << 7) + i;
    pe[base] = s;
    pe[base + 64] = co;
}

// ---------------- patch gather + 2D DFT + radial binning --------------------
__global__ void __launch_bounds__(256) fft_feat_kernel(const float* __restrict__ image,
                                                       const float* __restrict__ coords,
                                                       const float* __restrict__ fbi,
                                                       float* __restrict__ feat) {
    int pt = blockIdx.x;
    int b = pt >> 9;
    int tid = threadIdx.x;

    __shared__ float patch[16][16];
    __shared__ float Rre[16][9], Rim[16][9];
    __shared__ float twc[16], tws[16];
    __shared__ float bmag[8], bang[8];
    __shared__ int bcnt[8];
    __shared__ float smf[8];
    __shared__ int spx, spy;

    if (tid == 0) {
        float cx = coords[pt * 2];
        float cy = coords[pt * 2 + 1];
        int px = (int)cx; px = min(max(px, 8), 1015);
        int py = (int)cy; py = min(max(py, 8), 1015);
        spx = px; spy = py;
        float mx = -1e30f;
        for (int i = 0; i < 8; i++) mx = fmaxf(mx, fbi[i]);
        float s = 0.0f;
        for (int i = 0; i < 8; i++) { float e = expf(fbi[i] - mx); smf[i] = e; s += e; }
        float inv = 1.0f / s;
        for (int i = 0; i < 8; i++) smf[i] *= inv;
    }
    if (tid < 16) {
        twc[tid] = cospif((float)tid / 8.0f);
        tws[tid] = sinpif(-(float)tid / 8.0f);
    }
    if (tid < 8) { bmag[tid] = 0.0f; bang[tid] = 0.0f; bcnt[tid] = 0; }
    __syncthreads();

    int y = tid >> 4, x = tid & 15;
    int yy = spy - 8 + y, xx = spx - 8 + x;
    const float* imb = image + (size_t)b * 3u * 1024u * 1024u;
    size_t off = (size_t)yy * 1024 + xx;
    float gsum = imb[off] + imb[1048576u + off] + imb[2097152u + off];
    patch[y][x] = gsum * (1.0f / 3.0f);
    __syncthreads();

    if (tid < 144) {
        int ry = tid / 9, kx = tid % 9;
        float re = 0.0f, im = 0.0f;
#pragma unroll
        for (int j = 0; j < 16; j++) {
            float pv = patch[ry][j];
            int t = (kx * j) & 15;
            re += pv * twc[t];
            im += pv * tws[t];
        }
        Rre[ry][kx] = re;
        Rim[ry][kx] = im;
    }
    __syncthreads();

    if (tid < 144) {
        int ky = tid / 9, kx = tid % 9;
        float re = 0.0f, im = 0.0f;
#pragma unroll
        for (int j = 0; j < 16; j++) {
            int t = (ky * j) & 15;
            float c = twc[t], s = tws[t];
            float ar = Rre[j][kx], ai = Rim[j][kx];
            re += ar * c - ai * s;
            im += ar * s + ai * c;
        }
        re *= 0.0625f;
        im *= 0.0625f;
        float mag = sqrtf(re * re + im * im);
        float ang = atan2f(im, re);

        double fy = (ky < 8) ? (double)ky / 16.0 : ((double)ky - 16.0) / 16.0;
        double fx = (double)kx / 16.0;
        double r = sqrt(fx * fx + fy * fy);
        double maxr = 0.7071067811865476 + 1e-6;
        double step = maxr / 8.0;
        int bi = 0;
#pragma unroll
        for (int k = 1; k < 9; k++) if (r >= (double)k * step) bi = k;
        if (bi > 7) bi = 7;
        atomicAdd(&bmag[bi], mag);
        atomicAdd(&bang[bi], ang);
        atomicAdd(&bcnt[bi], 1);
    }
    __syncthreads();

    if (tid < 8) {
        float c = (float)max(bcnt[tid], 1);
        feat[(size_t)pt * 16 + tid]     = bmag[tid] / c * smf[tid];
        feat[(size_t)pt * 16 + 8 + tid] = bang[tid] / c;
    }
}

// ---------------- tensor-core GEMM (tf32 x3): C = A @ B(^T) -----------------
// 64x64 tile, 128 threads (4 warps, 2x2 of 32x32 warp tiles), double-buffered.
// BT=false: B is [N,K] row-major. BT=true: B is [K,N] row-major.
// EP: 0 bias, 1 bias+gelu, 2 bias+type_emb, 3 alpha-scale (no bias).
template <int EP, bool BT>
__global__ void __launch_bounds__(128) gemm_tc(
    const float* __restrict__ A, const float* __restrict__ B,
    const float* __restrict__ bias, float* __restrict__ C,
    int K, int lda, int ldb, int ldc,
    size_t sAb, size_t sAh, size_t sBb, size_t sBh, size_t sCb, size_t sCh,
    float alpha, const int* __restrict__ labels, const float* __restrict__ temb)
{
    __shared__ __align__(16) float As[2][16][72];
    __shared__ __align__(16) float Bs[2][16][72];

    const int z = blockIdx.z;
    A += (size_t)(z >> 2) * sAb + (size_t)(z & 3) * sAh;
    B += (size_t)(z >> 2) * sBb + (size_t)(z & 3) * sBh;
    C += (size_t)(z >> 2) * sCb + (size_t)(z & 3) * sCh;

    const int tid = threadIdx.x;
    const int m0 = blockIdx.y << 6, n0 = blockIdx.x << 6;

    // staging indices
    const int arow = tid >> 1, ak = (tid & 1) << 3;       // A/W: 64 rows x 16 k
    const int krow = tid >> 3, nc = (tid & 7) << 3;       // KN: 16 k x 64 n
    const float* Aptr = A + (size_t)(m0 + arow) * lda + ak;
    const float* Bptr = BT ? (B + (size_t)krow * ldb + n0 + nc)
                           : (B + (size_t)(n0 + arow) * ldb + ak);

    // mma lane mapping
    const int lane = tid & 31, wid = tid >> 5;
    const int g = lane >> 2, t4 = lane & 3;
    const int wm = (wid >> 1) << 5;    // warp m offset (0/32)
    const int wn = (wid & 1) << 5;     // warp n offset (0/32)

    float acc[2][4][4] = {};

    // preload tile 0
    {
        float4 a0 = *(const float4*)Aptr;
        float4 a1 = *(const float4*)(Aptr + 4);
        As[0][ak + 0][arow] = a0.x; As[0][ak + 1][arow] = a0.y;
        As[0][ak + 2][arow] = a0.z; As[0][ak + 3][arow] = a0.w;
        As[0][ak + 4][arow] = a1.x; As[0][ak + 5][arow] = a1.y;
        As[0][ak + 6][arow] = a1.z; As[0][ak + 7][arow] = a1.w;
        if (!BT) {
            float4 b0 = *(const float4*)Bptr;
            float4 b1 = *(const float4*)(Bptr + 4);
            Bs[0][ak + 0][arow] = b0.x; Bs[0][ak + 1][arow] = b0.y;
            Bs[0][ak + 2][arow] = b0.z; Bs[0][ak + 3][arow] = b0.w;
            Bs[0][ak + 4][arow] = b1.x; Bs[0][ak + 5][arow] = b1.y;
            Bs[0][ak + 6][arow] = b1.z; Bs[0][ak + 7][arow] = b1.w;
        } else {
            *(float4*)&Bs[0][krow][nc]     = *(const float4*)Bptr;
            *(float4*)&Bs[0][krow][nc + 4] = *(const float4*)(Bptr + 4);
        }
    }
    __syncthreads();

    int buf = 0;
    for (int k0 = 0; k0 < K; k0 += 16) {
        const bool notlast = (k0 + 16 < K);
        float4 pa0, pa1, pb0, pb1;
        if (notlast) {
            pa0 = *(const float4*)(Aptr + k0 + 16);
            pa1 = *(const float4*)(Aptr + k0 + 20);
            if (!BT) {
                pb0 = *(const float4*)(Bptr + k0 + 16);
                pb1 = *(const float4*)(Bptr + k0 + 20);
            } else {
                const float* bp = Bptr + (size_t)(k0 + 16) * ldb;
                pb0 = *(const float4*)bp;
                pb1 = *(const float4*)(bp + 4);
            }
        }

#pragma unroll
        for (int kk = 0; kk < 16; kk += 8) {
            unsigned ah[2][4], al[2][4];
#pragma unroll
            for (int mi = 0; mi < 2; mi++) {
                float a0 = As[buf][kk + t4][wm + mi * 16 + g];
                float a1 = As[buf][kk + t4][wm + mi * 16 + g + 8];
                float a2 = As[buf][kk + t4 + 4][wm + mi * 16 + g];
                float a3 = As[buf][kk + t4 + 4][wm + mi * 16 + g + 8];
                ah[mi][0] = tf32_rna(a0); al[mi][0] = __float_as_uint(a0 - __uint_as_float(ah[mi][0]));
                ah[mi][1] = tf32_rna(a1); al[mi][1] = __float_as_uint(a1 - __uint_as_float(ah[mi][1]));
                ah[mi][2] = tf32_rna(a2); al[mi][2] = __float_as_uint(a2 - __uint_as_float(ah[mi][2]));
                ah[mi][3] = tf32_rna(a3); al[mi][3] = __float_as_uint(a3 - __uint_as_float(ah[mi][3]));
            }
            unsigned bh[4][2], bl[4][2];
#pragma unroll
            for (int ni = 0; ni < 4; ni++) {
                float b0 = Bs[buf][kk + t4][wn + ni * 8 + g];
                float b1 = Bs[buf][kk + t4 + 4][wn + ni * 8 + g];
                bh[ni][0] = tf32_rna(b0); bl[ni][0] = __float_as_uint(b0 - __uint_as_float(bh[ni][0]));
                bh[ni][1] = tf32_rna(b1); bl[ni][1] = __float_as_uint(b1 - __uint_as_float(bh[ni][1]));
            }
#pragma unroll
            for (int mi = 0; mi < 2; mi++)
#pragma unroll
                for (int ni = 0; ni < 4; ni++) {
                    float* c = acc[mi][ni];
                    mma8(c, al[mi][0], al[mi][1], al[mi][2], al[mi][3], bh[ni][0], bh[ni][1]);
                    mma8(c, ah[mi][0], ah[mi][1], ah[mi][2], ah[mi][3], bl[ni][0], bl[ni][1]);
                    mma8(c, ah[mi][0], ah[mi][1], ah[mi][2], ah[mi][3], bh[ni][0], bh[ni][1]);
                }
        }

        if (notlast) {
            int nb = buf ^ 1;
            As[nb][ak + 0][arow] = pa0.x; As[nb][ak + 1][arow] = pa0.y;
            As[nb][ak + 2][arow] = pa0.z; As[nb][ak + 3][arow] = pa0.w;
            As[nb][ak + 4][arow] = pa1.x; As[nb][ak + 5][arow] = pa1.y;
            As[nb][ak + 6][arow] = pa1.z; As[nb][ak + 7][arow] = pa1.w;
            if (!BT) {
                Bs[nb][ak + 0][arow] = pb0.x; Bs[nb][ak + 1][arow] = pb0.y;
                Bs[nb][ak + 2][arow] = pb0.z; Bs[nb][ak + 3][arow] = pb0.w;
                Bs[nb][ak + 4][arow] = pb1.x; Bs[nb][ak + 5][arow] = pb1.y;
                Bs[nb][ak + 6][arow] = pb1.z; Bs[nb][ak + 7][arow] = pb1.w;
            } else {
                *(float4*)&Bs[nb][krow][nc]     = pb0;
                *(float4*)&Bs[nb][krow][nc + 4] = pb1;
            }
            __syncthreads();
            buf = nb;
        }
    }

    // epilogue
#pragma unroll
    for (int mi = 0; mi < 2; mi++) {
        int r0 = m0 + wm + mi * 16 + g;
        int r1 = r0 + 8;
        const float* t0 = nullptr;
        const float* t1 = nullptr;
        if (EP == 2) {
            t0 = temb + (size_t)labels[r0] * 256;
            t1 = temb + (size_t)labels[r1] * 256;
        }
#pragma unroll
        for (int ni = 0; ni < 4; ni++) {
            int c0 = n0 + wn + ni * 8 + (t4 << 1);
            float v00 = acc[mi][ni][0], v01 = acc[mi][ni][1];
            float v10 = acc[mi][ni][2], v11 = acc[mi][ni][3];
            if (EP == 3) {
                v00 *= alpha; v01 *= alpha; v10 *= alpha; v11 *= alpha;
            } else {
                float bx = bias[c0], by = bias[c0 + 1];
                v00 += bx; v01 += by; v10 += bx; v11 += by;
            }
            if (EP == 1) {
                v00 = gelu_f(v00); v01 = gelu_f(v01);
                v10 = gelu_f(v10); v11 = gelu_f(v11);
            }
            if (EP == 2) {
                v00 += t0[c0]; v01 += t0[c0 + 1];
                v10 += t1[c0]; v11 += t1[c0 + 1];
            }
            *(float2*)(C + (size_t)r0 * ldc + c0) = make_float2(v00, v01);
            *(float2*)(C + (size_t)r1 * ldc + c0) = make_float2(v10, v11);
        }
    }
}

// ---------------- softmax over 512-wide rows (in place) ---------------------
__global__ void __launch_bounds__(128) softmax512(float* __restrict__ S) {
    __shared__ float sh[4];
    size_t row = blockIdx.x;
    float4* p = (float4*)(S + row * 512);
    int t = threadIdx.x;
    float4 v = p[t];
    float m = fmaxf(fmaxf(v.x, v.y), fmaxf(v.z, v.w));
#pragma unroll
    for (int o = 16; o; o >>= 1) m = fmaxf(m, __shfl_xor_sync(0xffffffffu, m, o));
    if ((t & 31) == 0) sh[t >> 5] = m;
    __syncthreads();
    m = fmaxf(fmaxf(sh[0], sh[1]), fmaxf(sh[2], sh[3]));
    v.x = expf(v.x - m); v.y = expf(v.y - m);
    v.z = expf(v.z - m); v.w = expf(v.w - m);
    float s = v.x + v.y + v.z + v.w;
#pragma unroll
    for (int o = 16; o; o >>= 1) s += __shfl_xor_sync(0xffffffffu, s, o);
    __syncthreads();
    if ((t & 31) == 0) sh[t >> 5] = s;
    __syncthreads();
    s = sh[0] + sh[1] + sh[2] + sh[3];
    float inv = 1.0f / s;
    v.x *= inv; v.y *= inv; v.z *= inv; v.w *= inv;
    p[t] = v;
}

// ---------------- layer norm: warp per row ----------------------------------
template <int WIDTH, bool GELU, bool RES>
__global__ void __launch_bounds__(128) ln_warp(const float* __restrict__ in,
                                               const float* __restrict__ res,
                                               const float* __restrict__ g,
                                               const float* __restrict__ bv,
                                               float* __restrict__ out) {
    const int V4 = WIDTH / 128;
    int w = threadIdx.x >> 5, lane = threadIdx.x & 31;
    int row = (blockIdx.x << 2) + w;
    const float4* ip = (const float4*)(in + (size_t)row * WIDTH);
    const float4* rp = (const float4*)(res + (size_t)row * WIDTH);
    float4 v[V4];
    float s = 0.0f;
#pragma unroll
    for (int i = 0; i < V4; i++) {
        v[i] = ip[lane + 32 * i];
        if (RES) {
            float4 r = rp[lane + 32 * i];
            v[i].x += r.x; v[i].y += r.y; v[i].z += r.z; v[i].w += r.w;
        }
        s += v[i].x + v[i].y + v[i].z + v[i].w;
    }
#pragma unroll
    for (int o = 16; o; o >>= 1) s += __shfl_xor_sync(0xffffffffu, s, o);
    float mean = s * (1.0f / WIDTH);
    float q = 0.0f;
#pragma unroll
    for (int i = 0; i < V4; i++) {
        v[i].x -= mean; v[i].y -= mean; v[i].z -= mean; v[i].w -= mean;
        q += v[i].x * v[i].x + v[i].y * v[i].y + v[i].z * v[i].z + v[i].w * v[i].w;
    }
#pragma unroll
    for (int o = 16; o; o >>= 1) q += __shfl_xor_sync(0xffffffffu, q, o);
    float inv = rsqrtf(q * (1.0f / WIDTH) + 1e-5f);
    const float4* gp = (const float4*)g;
    const float4* bp = (const float4*)bv;
    float4* op = (float4*)(out + (size_t)row * WIDTH);
#pragma unroll
    for (int i = 0; i < V4; i++) {
        float4 gg = gp[lane + 32 * i], bb = bp[lane + 32 * i];
        float4 o;
        o.x = gg.x * v[i].x * inv + bb.x;
        o.y = gg.y * v[i].y * inv + bb.y;
        o.z = gg.z * v[i].z * inv + bb.z;
        o.w = gg.w * v[i].w * inv + bb.w;
        if (GELU) {
            o.x = gelu_f(o.x); o.y = gelu_f(o.y);
            o.z = gelu_f(o.z); o.w = gelu_f(o.w);
        }
        op[lane + 32 * i] = o;
    }
}

// ---------------- launch ----------------------------------------------------
extern "C" void kernel_launch(void* const* d_in, const int* in_sizes, int n_in,
                              void* d_out, int out_size) {
    (void)in_sizes; (void)n_in; (void)out_size;
    const float* image  = (const float*)d_in[0];
    const float* coords = (const float*)d_in[1];
    const int*   labels = (const int*)d_in[2];
    const float* pe_w   = (const float*)d_in[3];
    const float* pe_b   = (const float*)d_in[4];
    const float* temb   = (const float*)d_in[5];
    const float* fbi    = (const float*)d_in[6];
    const float* fe1_w  = (const float*)d_in[7];
    const float* fe1_b  = (const float*)d_in[8];
    const float* feln1g = (const float*)d_in[9];
    const float* feln1b = (const float*)d_in[10];
    const float* fe2_w  = (const float*)d_in[11];
    const float* fe2_b  = (const float*)d_in[12];
    const float* feln2g = (const float*)d_in[13];
    const float* feln2b = (const float*)d_in[14];
    const float* in_w   = (const float*)d_in[15];
    const float* in_b   = (const float*)d_in[16];
    const float* ao_w   = (const float*)d_in[17];
    const float* ao_b   = (const float*)d_in[18];
    const float* n1_g   = (const float*)d_in[19];
    const float* n1_b   = (const float*)d_in[20];
    const float* f1_w   = (const float*)d_in[21];
    const float* f1_b   = (const float*)d_in[22];
    const float* f2_w   = (const float*)d_in[23];
    const float* f2_b   = (const float*)d_in[24];
    const float* n2_g   = (const float*)d_in[25];
    const float* n2_b   = (const float*)d_in[26];
    const float* op_w   = (const float*)d_in[27];
    const float* op_b   = (const float*)d_in[28];
    float* out = (float*)d_out;

    float *p_pe, *p_spatial, *p_feat, *p_fe1, *p_h1, *p_fe2, *p_freq;
    float *p_q, *p_kv, *p_S, *p_o, *p_ao, *p_x, *p_ffh, *p_ff2, *p_x2;
    cudaGetSymbolAddress((void**)&p_pe, g_pe);
    cudaGetSymbolAddress((void**)&p_spatial, g_spatial);
    cudaGetSymbolAddress((void**)&p_feat, g_feat);
    cudaGetSymbolAddress((void**)&p_fe1, g_fe1);
    cudaGetSymbolAddress((void**)&p_h1, g_h1);
    cudaGetSymbolAddress((void**)&p_fe2, g_fe2);
    cudaGetSymbolAddress((void**)&p_freq, g_freq);
    cudaGetSymbolAddress((void**)&p_q, g_q);
    cudaGetSymbolAddress((void**)&p_kv, g_kv);
    cudaGetSymbolAddress((void**)&p_S, g_S);
    cudaGetSymbolAddress((void**)&p_o, g_o);
    cudaGetSymbolAddress((void**)&p_ao, g_ao);
    cudaGetSymbolAddress((void**)&p_x, g_x);
    cudaGetSymbolAddress((void**)&p_ffh, g_ffh);
    cudaGetSymbolAddress((void**)&p_ff2, g_ff2);
    cudaGetSymbolAddress((void**)&p_x2, g_x2);

    const size_t Z = 0;

    // 1) sinusoidal PE
    pe_kernel<<<PTS, 128>>>(coords, p_pe);
    // 2) spatial = PE @ pe_w^T + pe_b + type_emb[label]
    gemm_tc<2, false><<<dim3(4, 64, 1), 128>>>(p_pe, pe_w, pe_b, p_spatial,
        256, 256, 256, 256, Z, Z, Z, Z, Z, Z, 1.0f, labels, temb);
    // 3) patch FFT features
    fft_feat_kernel<<<PTS, 256>>>(image, coords, fbi, p_feat);
    // 4) freq MLP
    gemm_tc<0, false><<<dim3(2, 64, 1), 128>>>(p_feat, fe1_w, fe1_b, p_fe1,
        16, 16, 16, 128, Z, Z, Z, Z, Z, Z, 1.0f, nullptr, nullptr);
    ln_warp<128, true, false><<<PTS / 4, 128>>>(p_fe1, p_fe1, feln1g, feln1b, p_h1);
    gemm_tc<0, false><<<dim3(4, 64, 1), 128>>>(p_h1, fe2_w, fe2_b, p_fe2,
        128, 128, 128, 256, Z, Z, Z, Z, Z, Z, 1.0f, nullptr, nullptr);
    ln_warp<256, false, false><<<PTS / 4, 128>>>(p_fe2, p_fe2, feln2g, feln2b, p_freq);
    // 5) Q projection + fused K/V projection
    gemm_tc<0, false><<<dim3(4, 64, 1), 128>>>(p_spatial, in_w, in_b, p_q,
        256, 256, 256, 256, Z, Z, Z, Z, Z, Z, 1.0f, nullptr, nullptr);
    gemm_tc<0, false><<<dim3(8, 64, 1), 128>>>(p_freq, in_w + 65536, in_b + 256, p_kv,
        256, 256, 256, 512, Z, Z, Z, Z, Z, Z, 1.0f, nullptr, nullptr);
    // 6) attention: S = Q K^T / 8, softmax, O = P V
    gemm_tc<3, false><<<dim3(8, 8, 32), 128>>>(p_q, p_kv, nullptr, p_S,
        64, 256, 512, 512,
        (size_t)131072, (size_t)64, (size_t)262144, (size_t)64,
        (size_t)1048576, (size_t)262144, 0.125f, nullptr, nullptr);
    softmax512<<<32 * 512, 128>>>(p_S);
    gemm_tc<3, true><<<dim3(1, 8, 32), 128>>>(p_S, p_kv + 256, nullptr, p_o,
        512, 512, 512, 256,
        (size_t)1048576, (size_t)262144, (size_t)262144, (size_t)64,
        (size_t)131072, (size_t)64, 1.0f, nullptr, nullptr);
    // 7) attn out proj + residual LN
    gemm_tc<0, false><<<dim3(4, 64, 1), 128>>>(p_o, ao_w, ao_b, p_ao,
        256, 256, 256, 256, Z, Z, Z, Z, Z, Z, 1.0f, nullptr, nullptr);
    ln_warp<256, false, true><<<PTS / 4, 128>>>(p_ao, p_spatial, n1_g, n1_b, p_x);
    // 8) FFN
    gemm_tc<1, false><<<dim3(8, 64, 1), 128>>>(p_x, f1_w, f1_b, p_ffh,
        256, 256, 256, 512, Z, Z, Z, Z, Z, Z, 1.0f, nullptr, nullptr);
    gemm_tc<0, false><<<dim3(4, 64, 1), 128>>>(p_ffh, f2_w, f2_b, p_ff2,
        512, 512, 512, 256, Z, Z, Z, Z, Z, Z, 1.0f, nullptr, nullptr);
    ln_warp<256, false, true><<<PTS / 4, 128>>>(p_ff2, p_x, n2_g, n2_b, p_x2);
    // 9) output projection
    gemm_tc<0, false><<<dim3(4, 64, 1), 128>>>(p_x2, op_w, op_b, out,
        256, 256, 256, 256, Z, Z, Z, Z, Z, Z, 1.0f, nullptr, nullptr);
}

// round 7
// speedup vs baseline: 2.2806x; 1.0385x over previous
#include <cuda_runtime.h>
#include <math.h>

#define PTS 4096      // B*N = 8*512

// ---------------- scratch (device globals) ----------------------------------
__device__ float g_pe[PTS * 256];
__device__ float g_spatial[PTS * 256];
__device__ float g_feat[PTS * 16];
__device__ float g_fe1[PTS * 128];
__device__ float g_h1[PTS * 128];
__device__ float g_fe2[PTS * 256];
__device__ float g_freq[PTS * 256];
__device__ float g_qkv[PTS * 256 * 3];   // q | k | v stacked
__device__ float g_o[PTS * 256];
__device__ float g_ao[PTS * 256];
__device__ float g_x[PTS * 256];
__device__ float g_ffh[PTS * 512];
__device__ float g_ff2[PTS * 256];
__device__ float g_x2[PTS * 256];

__device__ __forceinline__ float gelu_f(float x) {
    return 0.5f * x * (1.0f + erff(x * 0.7071067811865475f));
}

// tf32 helpers ---------------------------------------------------------------
__device__ __forceinline__ unsigned tf32_rna(float x) {
    unsigned r;
    asm("cvt.rna.tf32.f32 %0, %1;" : "=r"(r) : "f"(x));
    return r;
}
__device__ __forceinline__ void mma8(float* c, unsigned a0, unsigned a1,
                                     unsigned a2, unsigned a3,
                                     unsigned b0, unsigned b1) {
    asm("mma.sync.aligned.m16n8k8.row.col.f32.tf32.tf32.f32 "
        "{%0,%1,%2,%3},{%4,%5,%6,%7},{%8,%9},{%0,%1,%2,%3};"
        : "+f"(c[0]), "+f"(c[1]), "+f"(c[2]), "+f"(c[3])
        : "r"(a0), "r"(a1), "r"(a2), "r"(a3), "r"(b0), "r"(b1));
}
// split helper
__device__ __forceinline__ void split_tf32(float x, unsigned& hi, unsigned& lo) {
    hi = tf32_rna(x);
    lo = __float_as_uint(x - __uint_as_float(hi));
}

// ---------------- PE kernel -------------------------------------------------
__global__ void __launch_bounds__(128) pe_kernel(const float* __restrict__ coords,
                                                 float* __restrict__ pe) {
    int pt = blockIdx.x, t = threadIdx.x;
    int i = t & 63, comp = t >> 6;
    float c = coords[pt * 2 + comp] * (1.0f / 1024.0f);
    float arg = c * 6.283185307179586f * exp2f(-(float)i * 0.4152410118609203f);
    float s, co;
    sincosf(arg, &s, &co);
    size_t base = (size_t)pt * 256 + (comp << 7) + i;
    pe[base] = s;
    pe[base + 64] = co;
}

// ---------------- patch gather + 2D DFT + radial binning --------------------
__global__ void __launch_bounds__(256) fft_feat_kernel(const float* __restrict__ image,
                                                       const float* __restrict__ coords,
                                                       const float* __restrict__ fbi,
                                                       float* __restrict__ feat) {
    int pt = blockIdx.x;
    int b = pt >> 9;
    int tid = threadIdx.x;

    __shared__ float patch[16][16];
    __shared__ float Rre[16][9], Rim[16][9];
    __shared__ float twc[16], tws[16];
    __shared__ float bmag[8], bang[8];
    __shared__ int bcnt[8];
    __shared__ float smf[8];
    __shared__ int spx, spy;

    if (tid == 0) {
        float cx = coords[pt * 2];
        float cy = coords[pt * 2 + 1];
        int px = (int)cx; px = min(max(px, 8), 1015);
        int py = (int)cy; py = min(max(py, 8), 1015);
        spx = px; spy = py;
        float mx = -1e30f;
        for (int i = 0; i < 8; i++) mx = fmaxf(mx, fbi[i]);
        float s = 0.0f;
        for (int i = 0; i < 8; i++) { float e = expf(fbi[i] - mx); smf[i] = e; s += e; }
        float inv = 1.0f / s;
        for (int i = 0; i < 8; i++) smf[i] *= inv;
    }
    if (tid < 16) {
        twc[tid] = cospif((float)tid / 8.0f);
        tws[tid] = sinpif(-(float)tid / 8.0f);
    }
    if (tid < 8) { bmag[tid] = 0.0f; bang[tid] = 0.0f; bcnt[tid] = 0; }
    __syncthreads();

    int y = tid >> 4, x = tid & 15;
    int yy = spy - 8 + y, xx = spx - 8 + x;
    const float* imb = image + (size_t)b * 3u * 1024u * 1024u;
    size_t off = (size_t)yy * 1024 + xx;
    float gsum = imb[off] + imb[1048576u + off] + imb[2097152u + off];
    patch[y][x] = gsum * (1.0f / 3.0f);
    __syncthreads();

    if (tid < 144) {
        int ry = tid / 9, kx = tid % 9;
        float re = 0.0f, im = 0.0f;
#pragma unroll
        for (int j = 0; j < 16; j++) {
            float pv = patch[ry][j];
            int t = (kx * j) & 15;
            re += pv * twc[t];
            im += pv * tws[t];
        }
        Rre[ry][kx] = re;
        Rim[ry][kx] = im;
    }
    __syncthreads();

    if (tid < 144) {
        int ky = tid / 9, kx = tid % 9;
        float re = 0.0f, im = 0.0f;
#pragma unroll
        for (int j = 0; j < 16; j++) {
            int t = (ky * j) & 15;
            float c = twc[t], s = tws[t];
            float ar = Rre[j][kx], ai = Rim[j][kx];
            re += ar * c - ai * s;
            im += ar * s + ai * c;
        }
        re *= 0.0625f;
        im *= 0.0625f;
        float mag = sqrtf(re * re + im * im);
        float ang = atan2f(im, re);

        double fy = (ky < 8) ? (double)ky / 16.0 : ((double)ky - 16.0) / 16.0;
        double fx = (double)kx / 16.0;
        double r = sqrt(fx * fx + fy * fy);
        double maxr = 0.7071067811865476 + 1e-6;
        double step = maxr / 8.0;
        int bi = 0;
#pragma unroll
        for (int k = 1; k < 9; k++) if (r >= (double)k * step) bi = k;
        if (bi > 7) bi = 7;
        atomicAdd(&bmag[bi], mag);
        atomicAdd(&bang[bi], ang);
        atomicAdd(&bcnt[bi], 1);
    }
    __syncthreads();

    if (tid < 8) {
        float c = (float)max(bcnt[tid], 1);
        feat[(size_t)pt * 16 + tid]     = bmag[tid] / c * smf[tid];
        feat[(size_t)pt * 16 + 8 + tid] = bang[tid] / c;
    }
}

// ---------------- tensor-core GEMM (tf32 x3): C = A @ B^T + bias ------------
// 64x64 tile, 128 threads (2x2 warp tiles of 32x32), double-buffered.
// EP: 0 bias, 1 bias+gelu, 2 bias+type_emb.
// QKV: gridDim.z=3; z=0 uses A, z>0 uses A2; W/bias/C offset by z slice.
template <int EP, bool QKV>
__global__ void __launch_bounds__(128) gemm_tc(
    const float* __restrict__ A, const float* __restrict__ B,
    const float* __restrict__ bias, float* __restrict__ C,
    int K, int lda, int ldb, int ldc,
    const int* __restrict__ labels, const float* __restrict__ temb,
    const float* __restrict__ A2)
{
    __shared__ __align__(16) float As[2][16][72];
    __shared__ __align__(16) float Bs[2][16][72];

    if (QKV) {
        const int z = blockIdx.z;
        if (z > 0) A = A2;
        B += (size_t)z * 65536;
        bias += z << 8;
        C += (size_t)z * (PTS * 256);
    }

    const int tid = threadIdx.x;
    const int m0 = blockIdx.y << 6, n0 = blockIdx.x << 6;

    const int arow = tid >> 1, ak = (tid & 1) << 3;       // 64 rows x 16 k
    const float* Aptr = A + (size_t)(m0 + arow) * lda + ak;
    const float* Bptr = B + (size_t)(n0 + arow) * ldb + ak;

    const int lane = tid & 31, wid = tid >> 5;
    const int g = lane >> 2, t4 = lane & 3;
    const int wm = (wid >> 1) << 5;
    const int wn = (wid & 1) << 5;

    float acc[2][4][4] = {};

    {
        float4 a0 = *(const float4*)Aptr;
        float4 a1 = *(const float4*)(Aptr + 4);
        As[0][ak + 0][arow] = a0.x; As[0][ak + 1][arow] = a0.y;
        As[0][ak + 2][arow] = a0.z; As[0][ak + 3][arow] = a0.w;
        As[0][ak + 4][arow] = a1.x; As[0][ak + 5][arow] = a1.y;
        As[0][ak + 6][arow] = a1.z; As[0][ak + 7][arow] = a1.w;
        float4 b0 = *(const float4*)Bptr;
        float4 b1 = *(const float4*)(Bptr + 4);
        Bs[0][ak + 0][arow] = b0.x; Bs[0][ak + 1][arow] = b0.y;
        Bs[0][ak + 2][arow] = b0.z; Bs[0][ak + 3][arow] = b0.w;
        Bs[0][ak + 4][arow] = b1.x; Bs[0][ak + 5][arow] = b1.y;
        Bs[0][ak + 6][arow] = b1.z; Bs[0][ak + 7][arow] = b1.w;
    }
    __syncthreads();

    int buf = 0;
    for (int k0 = 0; k0 < K; k0 += 16) {
        const bool notlast = (k0 + 16 < K);
        float4 pa0, pa1, pb0, pb1;
        if (notlast) {
            pa0 = *(const float4*)(Aptr + k0 + 16);
            pa1 = *(const float4*)(Aptr + k0 + 20);
            pb0 = *(const float4*)(Bptr + k0 + 16);
            pb1 = *(const float4*)(Bptr + k0 + 20);
        }

#pragma unroll
        for (int kk = 0; kk < 16; kk += 8) {
            unsigned ah[2][4], al[2][4];
#pragma unroll
            for (int mi = 0; mi < 2; mi++) {
                split_tf32(As[buf][kk + t4][wm + mi * 16 + g],     ah[mi][0], al[mi][0]);
                split_tf32(As[buf][kk + t4][wm + mi * 16 + g + 8], ah[mi][1], al[mi][1]);
                split_tf32(As[buf][kk + t4 + 4][wm + mi * 16 + g],     ah[mi][2], al[mi][2]);
                split_tf32(As[buf][kk + t4 + 4][wm + mi * 16 + g + 8], ah[mi][3], al[mi][3]);
            }
            unsigned bh[4][2], bl[4][2];
#pragma unroll
            for (int ni = 0; ni < 4; ni++) {
                split_tf32(Bs[buf][kk + t4][wn + ni * 8 + g],     bh[ni][0], bl[ni][0]);
                split_tf32(Bs[buf][kk + t4 + 4][wn + ni * 8 + g], bh[ni][1], bl[ni][1]);
            }
#pragma unroll
            for (int mi = 0; mi < 2; mi++)
#pragma unroll
                for (int ni = 0; ni < 4; ni++) {
                    float* c = acc[mi][ni];
                    mma8(c, al[mi][0], al[mi][1], al[mi][2], al[mi][3], bh[ni][0], bh[ni][1]);
                    mma8(c, ah[mi][0], ah[mi][1], ah[mi][2], ah[mi][3], bl[ni][0], bl[ni][1]);
                    mma8(c, ah[mi][0], ah[mi][1], ah[mi][2], ah[mi][3], bh[ni][0], bh[ni][1]);
                }
        }

        if (notlast) {
            int nb = buf ^ 1;
            As[nb][ak + 0][arow] = pa0.x; As[nb][ak + 1][arow] = pa0.y;
            As[nb][ak + 2][arow] = pa0.z; As[nb][ak + 3][arow] = pa0.w;
            As[nb][ak + 4][arow] = pa1.x; As[nb][ak + 5][arow] = pa1.y;
            As[nb][ak + 6][arow] = pa1.z; As[nb][ak + 7][arow] = pa1.w;
            Bs[nb][ak + 0][arow] = pb0.x; Bs[nb][ak + 1][arow] = pb0.y;
            Bs[nb][ak + 2][arow] = pb0.z; Bs[nb][ak + 3][arow] = pb0.w;
            Bs[nb][ak + 4][arow] = pb1.x; Bs[nb][ak + 5][arow] = pb1.y;
            Bs[nb][ak + 6][arow] = pb1.z; Bs[nb][ak + 7][arow] = pb1.w;
            __syncthreads();
            buf = nb;
        }
    }

#pragma unroll
    for (int mi = 0; mi < 2; mi++) {
        int r0 = m0 + wm + mi * 16 + g;
        int r1 = r0 + 8;
        const float* t0 = nullptr;
        const float* t1 = nullptr;
        if (EP == 2) {
            t0 = temb + (size_t)labels[r0] * 256;
            t1 = temb + (size_t)labels[r1] * 256;
        }
#pragma unroll
        for (int ni = 0; ni < 4; ni++) {
            int c0 = n0 + wn + ni * 8 + (t4 << 1);
            float v00 = acc[mi][ni][0], v01 = acc[mi][ni][1];
            float v10 = acc[mi][ni][2], v11 = acc[mi][ni][3];
            float bx = bias[c0], by = bias[c0 + 1];
            v00 += bx; v01 += by; v10 += bx; v11 += by;
            if (EP == 1) {
                v00 = gelu_f(v00); v01 = gelu_f(v01);
                v10 = gelu_f(v10); v11 = gelu_f(v11);
            }
            if (EP == 2) {
                v00 += t0[c0]; v01 += t0[c0 + 1];
                v10 += t1[c0]; v11 += t1[c0 + 1];
            }
            *(float2*)(C + (size_t)r0 * ldc + c0) = make_float2(v00, v01);
            *(float2*)(C + (size_t)r1 * ldc + c0) = make_float2(v10, v11);
        }
    }
}

// ---------------- fused attention (flash-style, tf32 x3) --------------------
// grid (8 q-tiles, 4 heads, 8 batch), 128 threads.
__global__ void __launch_bounds__(128) attn_fused(const float* __restrict__ QKVb,
                                                  float* __restrict__ O) {
    __shared__ __align__(16) float Qs[64][68];
    __shared__ __align__(16) float Ks[64][36];   // [d][kpos]
    __shared__ __align__(16) float Vs[32][68];   // [kpos][d]
    __shared__ __align__(16) float Ss[64][36];   // [q][kpos]
    __shared__ float rm[64], rl[64], rf[64];

    const int b = blockIdx.z, h = blockIdx.y, q0 = blockIdx.x << 6;
    const int tid = threadIdx.x;
    const int lane = tid & 31, wid = tid >> 5;
    const int g = lane >> 2, t4 = lane & 3;

    const float* Qg = QKVb + ((size_t)(b * 512 + q0)) * 256 + h * 64;
    const float* Kg = QKVb + (size_t)PTS * 256 + ((size_t)b * 512) * 256 + h * 64;
    const float* Vg = QKVb + (size_t)PTS * 512 + ((size_t)b * 512) * 256 + h * 64;

    {   // load Q tile
        int m = tid >> 1, d0 = (tid & 1) << 5;
        const float* src = Qg + (size_t)m * 256 + d0;
#pragma unroll
        for (int i = 0; i < 8; i++)
            *(float4*)&Qs[m][d0 + i * 4] = *(const float4*)(src + i * 4);
    }
    if (tid < 64) { rm[tid] = -1e30f; rl[tid] = 0.0f; }

    const int wm = (wid >> 1) << 5, wn = (wid & 1) << 5;
    const int sm = wid << 4;     // S-stage: warp owns 16 q-rows
    float oacc[2][4][4] = {};

    for (int kc = 0; kc < 512; kc += 32) {
        __syncthreads();
        {   // stage K (transposed) and V chunks
            int i = tid >> 2, d0 = (tid & 3) << 4;
            const float* ksrc = Kg + (size_t)(kc + i) * 256 + d0;
            const float* vsrc = Vg + (size_t)(kc + i) * 256 + d0;
#pragma unroll
            for (int j = 0; j < 4; j++) {
                float4 v = *(const float4*)(ksrc + j * 4);
                Ks[d0 + j * 4 + 0][i] = v.x;
                Ks[d0 + j * 4 + 1][i] = v.y;
                Ks[d0 + j * 4 + 2][i] = v.z;
                Ks[d0 + j * 4 + 3][i] = v.w;
                *(float4*)&Vs[i][d0 + j * 4] = *(const float4*)(vsrc + j * 4);
            }
        }
        __syncthreads();

        // S = Q K^T * 0.125 — warp computes its 16 rows x 32 cols
        float sacc[4][4] = {};
#pragma unroll
        for (int kk = 0; kk < 64; kk += 8) {
            unsigned ah0, ah1, ah2, ah3, al0, al1, al2, al3;
            split_tf32(Qs[sm + g][kk + t4],         ah0, al0);
            split_tf32(Qs[sm + g + 8][kk + t4],     ah1, al1);
            split_tf32(Qs[sm + g][kk + t4 + 4],     ah2, al2);
            split_tf32(Qs[sm + g + 8][kk + t4 + 4], ah3, al3);
#pragma unroll
            for (int ni = 0; ni < 4; ni++) {
                unsigned bh0, bh1, bl0, bl1;
                split_tf32(Ks[kk + t4][ni * 8 + g],     bh0, bl0);
                split_tf32(Ks[kk + t4 + 4][ni * 8 + g], bh1, bl1);
                mma8(sacc[ni], al0, al1, al2, al3, bh0, bh1);
                mma8(sacc[ni], ah0, ah1, ah2, ah3, bl0, bl1);
                mma8(sacc[ni], ah0, ah1, ah2, ah3, bh0, bh1);
            }
        }
#pragma unroll
        for (int ni = 0; ni < 4; ni++) {
            int c = (ni << 3) + (t4 << 1);
            Ss[sm + g][c]         = sacc[ni][0] * 0.125f;
            Ss[sm + g][c + 1]     = sacc[ni][1] * 0.125f;
            Ss[sm + g + 8][c]     = sacc[ni][2] * 0.125f;
            Ss[sm + g + 8][c + 1] = sacc[ni][3] * 0.125f;
        }
        __syncthreads();

        // online softmax update (thread t handles row t)
        if (tid < 64) {
            float mold = rm[tid];
            float mx = mold;
#pragma unroll
            for (int j = 0; j < 32; j++) mx = fmaxf(mx, Ss[tid][j]);
            float f = __expf(mold - mx);
            float sum = 0.0f;
#pragma unroll
            for (int j = 0; j < 32; j++) {
                float p = __expf(Ss[tid][j] - mx);
                Ss[tid][j] = p;
                sum += p;
            }
            rl[tid] = rl[tid] * f + sum;
            rm[tid] = mx;
            rf[tid] = f;
        }
        __syncthreads();

        // rescale accumulators, then O += P V
#pragma unroll
        for (int mi = 0; mi < 2; mi++) {
            float f0 = rf[wm + (mi << 4) + g];
            float f1 = rf[wm + (mi << 4) + g + 8];
#pragma unroll
            for (int ni = 0; ni < 4; ni++) {
                oacc[mi][ni][0] *= f0; oacc[mi][ni][1] *= f0;
                oacc[mi][ni][2] *= f1; oacc[mi][ni][3] *= f1;
            }
        }
#pragma unroll
        for (int kk = 0; kk < 32; kk += 8) {
            unsigned ah[2][4], al[2][4];
#pragma unroll
            for (int mi = 0; mi < 2; mi++) {
                split_tf32(Ss[wm + (mi << 4) + g][kk + t4],         ah[mi][0], al[mi][0]);
                split_tf32(Ss[wm + (mi << 4) + g + 8][kk + t4],     ah[mi][1], al[mi][1]);
                split_tf32(Ss[wm + (mi << 4) + g][kk + t4 + 4],     ah[mi][2], al[mi][2]);
                split_tf32(Ss[wm + (mi << 4) + g + 8][kk + t4 + 4], ah[mi][3], al[mi][3]);
            }
#pragma unroll
            for (int ni = 0; ni < 4; ni++) {
                unsigned bh0, bh1, bl0, bl1;
                split_tf32(Vs[kk + t4][wn + ni * 8 + g],     bh0, bl0);
                split_tf32(Vs[kk + t4 + 4][wn + ni * 8 + g], bh1, bl1);
#pragma unroll
                for (int mi = 0; mi < 2; mi++) {
                    float* c = oacc[mi][ni];
                    mma8(c, al[mi][0], al[mi][1], al[mi][2], al[mi][3], bh0, bh1);
                    mma8(c, ah[mi][0], ah[mi][1], ah[mi][2], ah[mi][3], bl0, bl1);
                    mma8(c, ah[mi][0], ah[mi][1], ah[mi][2], ah[mi][3], bh0, bh1);
                }
            }
        }
    }

    float* Og = O + ((size_t)(b * 512 + q0)) * 256 + h * 64;
#pragma unroll
    for (int mi = 0; mi < 2; mi++) {
        int r0 = wm + (mi << 4) + g, r1 = r0 + 8;
        float il0 = 1.0f / rl[r0], il1 = 1.0f / rl[r1];
#pragma unroll
        for (int ni = 0; ni < 4; ni++) {
            int c = wn + (ni << 3) + (t4 << 1);
            *(float2*)(Og + (size_t)r0 * 256 + c) =
                make_float2(oacc[mi][ni][0] * il0, oacc[mi][ni][1] * il0);
            *(float2*)(Og + (size_t)r1 * 256 + c) =
                make_float2(oacc[mi][ni][2] * il1, oacc[mi][ni][3] * il1);
        }
    }
}

// ---------------- layer norm: warp per row ----------------------------------
template <int WIDTH, bool GELU, bool RES>
__global__ void __launch_bounds__(128) ln_warp(const float* __restrict__ in,
                                               const float* __restrict__ res,
                                               const float* __restrict__ g,
                                               const float* __restrict__ bv,
                                               float* __restrict__ out) {
    const int V4 = WIDTH / 128;
    int w = threadIdx.x >> 5, lane = threadIdx.x & 31;
    int row = (blockIdx.x << 2) + w;
    const float4* ip = (const float4*)(in + (size_t)row * WIDTH);
    const float4* rp = (const float4*)(res + (size_t)row * WIDTH);
    float4 v[V4];
    float s = 0.0f;
#pragma unroll
    for (int i = 0; i < V4; i++) {
        v[i] = ip[lane + 32 * i];
        if (RES) {
            float4 r = rp[lane + 32 * i];
            v[i].x += r.x; v[i].y += r.y; v[i].z += r.z; v[i].w += r.w;
        }
        s += v[i].x + v[i].y + v[i].z + v[i].w;
    }
#pragma unroll
    for (int o = 16; o; o >>= 1) s += __shfl_xor_sync(0xffffffffu, s, o);
    float mean = s * (1.0f / WIDTH);
    float q = 0.0f;
#pragma unroll
    for (int i = 0; i < V4; i++) {
        v[i].x -= mean; v[i].y -= mean; v[i].z -= mean; v[i].w -= mean;
        q += v[i].x * v[i].x + v[i].y * v[i].y + v[i].z * v[i].z + v[i].w * v[i].w;
    }
#pragma unroll
    for (int o = 16; o; o >>= 1) q += __shfl_xor_sync(0xffffffffu, q, o);
    float inv = rsqrtf(q * (1.0f / WIDTH) + 1e-5f);
    const float4* gp = (const float4*)g;
    const float4* bp = (const float4*)bv;
    float4* op = (float4*)(out + (size_t)row * WIDTH);
#pragma unroll
    for (int i = 0; i < V4; i++) {
        float4 gg = gp[lane + 32 * i], bb = bp[lane + 32 * i];
        float4 o;
        o.x = gg.x * v[i].x * inv + bb.x;
        o.y = gg.y * v[i].y * inv + bb.y;
        o.z = gg.z * v[i].z * inv + bb.z;
        o.w = gg.w * v[i].w * inv + bb.w;
        if (GELU) {
            o.x = gelu_f(o.x); o.y = gelu_f(o.y);
            o.z = gelu_f(o.z); o.w = gelu_f(o.w);
        }
        op[lane + 32 * i] = o;
    }
}

// ---------------- launch ----------------------------------------------------
extern "C" void kernel_launch(void* const* d_in, const int* in_sizes, int n_in,
                              void* d_out, int out_size) {
    (void)in_sizes; (void)n_in; (void)out_size;
    const float* image  = (const float*)d_in[0];
    const float* coords = (const float*)d_in[1];
    const int*   labels = (const int*)d_in[2];
    const float* pe_w   = (const float*)d_in[3];
    const float* pe_b   = (const float*)d_in[4];
    const float* temb   = (const float*)d_in[5];
    const float* fbi    = (const float*)d_in[6];
    const float* fe1_w  = (const float*)d_in[7];
    const float* fe1_b  = (const float*)d_in[8];
    const float* feln1g = (const float*)d_in[9];
    const float* feln1b = (const float*)d_in[10];
    const float* fe2_w  = (const float*)d_in[11];
    const float* fe2_b  = (const float*)d_in[12];
    const float* feln2g = (const float*)d_in[13];
    const float* feln2b = (const float*)d_in[14];
    const float* in_w   = (const float*)d_in[15];
    const float* in_b   = (const float*)d_in[16];
    const float* ao_w   = (const float*)d_in[17];
    const float* ao_b   = (const float*)d_in[18];
    const float* n1_g   = (const float*)d_in[19];
    const float* n1_b   = (const float*)d_in[20];
    const float* f1_w   = (const float*)d_in[21];
    const float* f1_b   = (const float*)d_in[22];
    const float* f2_w   = (const float*)d_in[23];
    const float* f2_b   = (const float*)d_in[24];
    const float* n2_g   = (const float*)d_in[25];
    const float* n2_b   = (const float*)d_in[26];
    const float* op_w   = (const float*)d_in[27];
    const float* op_b   = (const float*)d_in[28];
    float* out = (float*)d_out;

    float *p_pe, *p_spatial, *p_feat, *p_fe1, *p_h1, *p_fe2, *p_freq;
    float *p_qkv, *p_o, *p_ao, *p_x, *p_ffh, *p_ff2, *p_x2;
    cudaGetSymbolAddress((void**)&p_pe, g_pe);
    cudaGetSymbolAddress((void**)&p_spatial, g_spatial);
    cudaGetSymbolAddress((void**)&p_feat, g_feat);
    cudaGetSymbolAddress((void**)&p_fe1, g_fe1);
    cudaGetSymbolAddress((void**)&p_h1, g_h1);
    cudaGetSymbolAddress((void**)&p_fe2, g_fe2);
    cudaGetSymbolAddress((void**)&p_freq, g_freq);
    cudaGetSymbolAddress((void**)&p_qkv, g_qkv);
    cudaGetSymbolAddress((void**)&p_o, g_o);
    cudaGetSymbolAddress((void**)&p_ao, g_ao);
    cudaGetSymbolAddress((void**)&p_x, g_x);
    cudaGetSymbolAddress((void**)&p_ffh, g_ffh);
    cudaGetSymbolAddress((void**)&p_ff2, g_ff2);
    cudaGetSymbolAddress((void**)&p_x2, g_x2);

    // 1) sinusoidal PE
    pe_kernel<<<PTS, 128>>>(coords, p_pe);
    // 2) spatial = PE @ pe_w^T + pe_b + type_emb[label]
    gemm_tc<2, false><<<dim3(4, 64, 1), 128>>>(p_pe, pe_w, pe_b, p_spatial,
        256, 256, 256, 256, labels, temb, nullptr);
    // 3) patch FFT features
    fft_feat_kernel<<<PTS, 256>>>(image, coords, fbi, p_feat);
    // 4) freq MLP
    gemm_tc<0, false><<<dim3(2, 64, 1), 128>>>(p_feat, fe1_w, fe1_b, p_fe1,
        16, 16, 16, 128, nullptr, nullptr, nullptr);
    ln_warp<128, true, false><<<PTS / 4, 128>>>(p_fe1, p_fe1, feln1g, feln1b, p_h1);
    gemm_tc<0, false><<<dim3(4, 64, 1), 128>>>(p_h1, fe2_w, fe2_b, p_fe2,
        128, 128, 128, 256, nullptr, nullptr, nullptr);
    ln_warp<256, false, false><<<PTS / 4, 128>>>(p_fe2, p_fe2, feln2g, feln2b, p_freq);
    // 5) fused Q/K/V projections (z = 0,1,2)
    gemm_tc<0, true><<<dim3(4, 64, 3), 128>>>(p_spatial, in_w, in_b, p_qkv,
        256, 256, 256, 256, nullptr, nullptr, p_freq);
    // 6) fused attention
    attn_fused<<<dim3(8, 4, 8), 128>>>(p_qkv, p_o);
    // 7) attn out proj + residual LN
    gemm_tc<0, false><<<dim3(4, 64, 1), 128>>>(p_o, ao_w, ao_b, p_ao,
        256, 256, 256, 256, nullptr, nullptr, nullptr);
    ln_warp<256, false, true><<<PTS / 4, 128>>>(p_ao, p_spatial, n1_g, n1_b, p_x);
    // 8) FFN
    gemm_tc<1, false><<<dim3(8, 64, 1), 128>>>(p_x, f1_w, f1_b, p_ffh,
        256, 256, 256, 512, nullptr, nullptr, nullptr);
    gemm_tc<0, false><<<dim3(4, 64, 1), 128>>>(p_ffh, f2_w, f2_b, p_ff2,
        512, 512, 512, 256, nullptr, nullptr, nullptr);
    ln_warp<256, false, true><<<PTS / 4, 128>>>(p_ff2, p_x, n2_g, n2_b, p_x2);
    // 9) output projection
    gemm_tc<0, false><<<dim3(4, 64, 1), 128>>>(p_x2, op_w, op_b, out,
        256, 256, 256, 256, nullptr, nullptr, nullptr);
}